// round 13
// baseline (speedup 1.0000x reference)
#include <cuda_runtime.h>
#include <cuda_fp16.h>
#include <math.h>
#include <stdint.h>

typedef unsigned short ushort_t;

// ---------------------------------------------------------------------------
// Scratch (device globals; no runtime allocation allowed)
// ---------------------------------------------------------------------------
__device__ __half   g_KVh[(size_t)32768 * 2048];    // [B*S, 2048]: K | V (fp16)
__device__ ushort_t g_srcH[(size_t)32768 * 1024];   // src fp16
__device__ ushort_t g_wkvH[(size_t)2048 * 1024];    // [Wk|Wv]^T fp16 : [n][k]
__device__ __half   g_Qh[(size_t)1024 * 1024];      // Q fp16 (pre-scaled by 1/8)
__device__ float    g_A [(size_t)1024 * 1024];
__device__ float    g_F1[(size_t)1024 * 1024];
__device__ float    g_T1[(size_t)1024 * 256];
__device__ float    g_X1[(size_t)1024 * 256];

// ---------------------------------------------------------------------------
// helpers
// ---------------------------------------------------------------------------
__device__ __forceinline__ void mma16816h(float* c, const uint32_t* a, uint32_t b0, uint32_t b1) {
    asm volatile(
        "mma.sync.aligned.m16n8k16.row.col.f32.f16.f16.f32 "
        "{%0,%1,%2,%3}, {%4,%5,%6,%7}, {%8,%9}, {%0,%1,%2,%3};"
        : "+f"(c[0]), "+f"(c[1]), "+f"(c[2]), "+f"(c[3])
        : "r"(a[0]), "r"(a[1]), "r"(a[2]), "r"(a[3]), "r"(b0), "r"(b1));
}

__device__ __forceinline__ void ldsm4(uint32_t* r, uint32_t saddr) {
    asm volatile(
        "ldmatrix.sync.aligned.m8n8.x4.shared.b16 {%0,%1,%2,%3}, [%4];"
        : "=r"(r[0]), "=r"(r[1]), "=r"(r[2]), "=r"(r[3]) : "r"(saddr));
}

__device__ __forceinline__ void cp16(void* sdst, const void* gsrc) {
    uint32_t s = (uint32_t)__cvta_generic_to_shared(sdst);
    asm volatile("cp.async.cg.shared.global [%0], [%1], 16;" :: "r"(s), "l"(gsrc));
}

__device__ __forceinline__ uint32_t smem_u32(const void* p) {
    return (uint32_t)__cvta_generic_to_shared(p);
}

__device__ __forceinline__ uint32_t pack2h(ushort_t lo, ushort_t hi) {
    return (uint32_t)lo | ((uint32_t)hi << 16);
}

// ---------------------------------------------------------------------------
// pre-pass: fp32 -> fp16 (flat, float4 granularity)
// ---------------------------------------------------------------------------
__global__ __launch_bounds__(256) void convert_src_kernel(
    const float* __restrict__ x, ushort_t* __restrict__ H, int n4)
{
    int i = blockIdx.x * blockDim.x + threadIdx.x;
    if (i >= n4) return;
    float4 v = ((const float4*)x)[i];
    __half2 h0 = __floats2half2_rn(v.x, v.y);
    __half2 h1 = __floats2half2_rn(v.z, v.w);
    ((uint2*)H)[i] = make_uint2(*(uint32_t*)&h0, *(uint32_t*)&h1);
}

// ---------------------------------------------------------------------------
// pre-pass: WT[n][k] = (n<1024 ? Wk[k][n] : Wv[k][n-1024]) -> fp16
// ---------------------------------------------------------------------------
__global__ __launch_bounds__(256) void conv_wkv_kernel(
    const float* __restrict__ Wk, const float* __restrict__ Wv,
    ushort_t* __restrict__ H)
{
    __shared__ float tile[32][33];
    const int n0 = blockIdx.x * 32, k0 = blockIdx.y * 32;
    const float* W = (n0 < 1024) ? Wk : Wv;
    const int nofs = (n0 < 1024) ? n0 : n0 - 1024;
    for (int r = threadIdx.y; r < 32; r += 8)
        tile[r][threadIdx.x] = W[(size_t)(k0 + r) * 1024 + nofs + threadIdx.x];
    __syncthreads();
    for (int r = threadIdx.y; r < 32; r += 8) {
        float v = tile[threadIdx.x][r];
        size_t o = (size_t)(n0 + r) * 1024 + k0 + threadIdx.x;
        H[o] = __half_as_ushort(__float2half_rn(v));
    }
}

// ---------------------------------------------------------------------------
// Fused KV GEMM: KVh[32768,2048] = src @ WkvT^T + bias, fp16 in/out.
// Block tile 128x128, BK=32, 3-stage cp.async pipeline, ldmatrix fragments,
// ONE __syncthreads per stage. __launch_bounds__(256,3) -> 3 CTAs/SM.
// Stage: A 128x32 + B 128x32 halves, pitch 40 -> 20480 B; 3 stages = 61440 B.
// ---------------------------------------------------------------------------
#define TPK 40
#define KV_BOFF (128 * TPK)                 // halves offset of B tile in stage
#define KV_STAGE_H (2 * 128 * TPK)          // halves per stage
#define KV_SMEM_BYTES (3 * KV_STAGE_H * 2)  // 61440

__global__ __launch_bounds__(256, 3) void gemm_kv_f16(
    const ushort_t* __restrict__ srcH,
    const ushort_t* __restrict__ wtH,
    const float* __restrict__ bk, const float* __restrict__ bv,
    __half* __restrict__ C)
{
    extern __shared__ ushort_t smem[];

    const int tid  = threadIdx.x;
    const int lane = tid & 31;
    const int wid  = tid >> 5;
    const int wm   = wid & 3;
    const int wn   = wid >> 2;
    const int g    = lane >> 2;
    const int tig  = lane & 3;

    const int r0 = blockIdx.y * 128;
    const int c0 = blockIdx.x * 128;

    float acc[2][8][4];
#pragma unroll
    for (int mt = 0; mt < 2; mt++)
#pragma unroll
        for (int nt = 0; nt < 8; nt++)
#pragma unroll
            for (int j = 0; j < 4; j++) acc[mt][nt][j] = 0.f;

    // stage loader: 4 cp16 per thread (A 512 chunks + B 512 chunks)
    auto load_stage = [&](ushort_t* stg, int kb) {
#pragma unroll
        for (int j = 0; j < 2; j++) {
            int cc  = tid + 256 * j;          // 0..511
            int row = cc >> 2;
            int c16 = (cc & 3) * 8;
            cp16(&stg[row * TPK + c16], srcH + (size_t)(r0 + row) * 1024 + kb + c16);
        }
#pragma unroll
        for (int j = 0; j < 2; j++) {
            int cc  = tid + 256 * j;
            int row = cc >> 2;
            int c16 = (cc & 3) * 8;
            cp16(&stg[KV_BOFF + row * TPK + c16], wtH + (size_t)(c0 + row) * 1024 + kb + c16);
        }
    };

    const int lrow = lane & 15;
    const int lcol = (lane >> 4) * 8;

    ushort_t* stgs[3] = {smem, smem + KV_STAGE_H, smem + 2 * KV_STAGE_H};

    load_stage(stgs[0], 0);
    asm volatile("cp.async.commit_group;" ::: "memory");
    load_stage(stgs[1], 32);
    asm volatile("cp.async.commit_group;" ::: "memory");

    for (int it = 0; it < 32; it++) {
        if (it < 31) {
            asm volatile("cp.async.wait_group 1;" ::: "memory");
        } else {
            asm volatile("cp.async.wait_group 0;" ::: "memory");
        }
        __syncthreads();

        if (it + 2 < 32) {
            load_stage(stgs[(it + 2) % 3], (it + 2) * 32);
            asm volatile("cp.async.commit_group;" ::: "memory");
        }

        ushort_t* stg = stgs[it % 3];
        const uint32_t aBase = smem_u32(&stg[(wm * 32 + lrow) * TPK + lcol]);
        const uint32_t bBase = smem_u32(&stg[KV_BOFF + (wn * 64 + lrow) * TPK + lcol]);

#pragma unroll
        for (int ks = 0; ks < 2; ks++) {
            uint32_t A0[4], A1[4];
            ldsm4(A0, aBase + ks * 32);
            ldsm4(A1, aBase + (uint32_t)(16 * TPK * 2) + ks * 32);
#pragma unroll
            for (int p = 0; p < 4; p++) {
                uint32_t bb[4];
                ldsm4(bb, bBase + (uint32_t)(p * 16 * TPK * 2) + ks * 32);
                mma16816h(acc[0][2 * p],     A0, bb[0], bb[2]);
                mma16816h(acc[1][2 * p],     A1, bb[0], bb[2]);
                mma16816h(acc[0][2 * p + 1], A0, bb[1], bb[3]);
                mma16816h(acc[1][2 * p + 1], A1, bb[1], bb[3]);
            }
        }
    }

    // epilogue: bias add in fp32, store fp16
#pragma unroll
    for (int mt = 0; mt < 2; mt++) {
        int r = r0 + wm * 32 + mt * 16 + g;
#pragma unroll
        for (int nt = 0; nt < 8; nt++) {
            int col = c0 + wn * 64 + nt * 8 + tig * 2;
            float b0 = (col < 1024) ? bk[col] : bv[col - 1024];
            float b1 = (col + 1 < 1024) ? bk[col + 1] : bv[col + 1 - 1024];
            *(__half2*)(C + (size_t)r * 2048 + col) =
                __floats2half2_rn(acc[mt][nt][0] + b0, acc[mt][nt][1] + b1);
            *(__half2*)(C + (size_t)(r + 8) * 2048 + col) =
                __floats2half2_rn(acc[mt][nt][2] + b0, acc[mt][nt][3] + b1);
        }
    }
}

// ---------------------------------------------------------------------------
// Small GEMM: fp32 in, register-prefetch pipelined, single fp16 MMA.
// HOUT: write __half with oscale folded; else fp32 (+optional ReLU).
// ---------------------------------------------------------------------------
#define A_PITCH 40
#define B_PITCH 136

template<bool RELU, bool HOUT>
__global__ __launch_bounds__(256) void gemm_tc(
    const float* __restrict__ A, int lda,
    const float* __restrict__ W, int ldb,
    const float* __restrict__ bias,
    void* __restrict__ Cv, int ldc, int K, float oscale)
{
    __shared__ ushort_t AsH[128 * A_PITCH];
    __shared__ ushort_t BsH[32 * B_PITCH];

    const int tid  = threadIdx.x;
    const int lane = tid & 31;
    const int wid  = tid >> 5;
    const int wm   = wid & 3;
    const int wn   = wid >> 2;
    const int g    = lane >> 2;
    const int tig  = lane & 3;

    const int r0 = blockIdx.y * 128;
    const int c0 = blockIdx.x * 128;

    float acc[2][8][4];
#pragma unroll
    for (int mt = 0; mt < 2; mt++)
#pragma unroll
        for (int nt = 0; nt < 8; nt++)
#pragma unroll
            for (int j = 0; j < 4; j++) acc[mt][nt][j] = 0.f;

    float4 aR[4], bR[4];
#pragma unroll
    for (int i = 0; i < 4; i++) {
        int flat = tid + 256 * i;
        aR[i] = *(const float4*)(A + (size_t)(r0 + (flat >> 3)) * lda + (flat & 7) * 4);
        bR[i] = *(const float4*)(W + (size_t)(flat >> 5) * ldb + c0 + (flat & 31) * 4);
    }

    for (int kb = 0; kb < K; kb += 32) {
#pragma unroll
        for (int i = 0; i < 4; i++) {
            int flat = tid + 256 * i;
            int row = flat >> 3;
            int kc  = (flat & 7) * 4;
            __half2 h0 = __floats2half2_rn(aR[i].x, aR[i].y);
            __half2 h1 = __floats2half2_rn(aR[i].z, aR[i].w);
            *(uint32_t*)&AsH[row * A_PITCH + kc]     = *(uint32_t*)&h0;
            *(uint32_t*)&AsH[row * A_PITCH + kc + 2] = *(uint32_t*)&h1;
            int kr = flat >> 5;
            int nc = (flat & 31) * 4;
            __half2 g0 = __floats2half2_rn(bR[i].x, bR[i].y);
            __half2 g1 = __floats2half2_rn(bR[i].z, bR[i].w);
            *(uint32_t*)&BsH[kr * B_PITCH + nc]     = *(uint32_t*)&g0;
            *(uint32_t*)&BsH[kr * B_PITCH + nc + 2] = *(uint32_t*)&g1;
        }
        __syncthreads();

        if (kb + 32 < K) {
#pragma unroll
            for (int i = 0; i < 4; i++) {
                int flat = tid + 256 * i;
                aR[i] = *(const float4*)(A + (size_t)(r0 + (flat >> 3)) * lda + kb + 32 + (flat & 7) * 4);
                bR[i] = *(const float4*)(W + (size_t)(kb + 32 + (flat >> 5)) * ldb + c0 + (flat & 31) * 4);
            }
        }

#pragma unroll
        for (int ks = 0; ks < 32; ks += 16) {
            uint32_t aH[2][4];
#pragma unroll
            for (int mt = 0; mt < 2; mt++) {
                int rA = wm * 32 + mt * 16 + g;
                int cA = ks + tig * 2;
                aH[mt][0] = *(const uint32_t*)&AsH[rA * A_PITCH + cA];
                aH[mt][1] = *(const uint32_t*)&AsH[(rA + 8) * A_PITCH + cA];
                aH[mt][2] = *(const uint32_t*)&AsH[rA * A_PITCH + cA + 8];
                aH[mt][3] = *(const uint32_t*)&AsH[(rA + 8) * A_PITCH + cA + 8];
            }
#pragma unroll
            for (int nt = 0; nt < 8; nt++) {
                int col = wn * 64 + nt * 8 + g;
                int rb  = (ks + tig * 2) * B_PITCH + col;
                uint32_t bH0 = pack2h(BsH[rb], BsH[rb + B_PITCH]);
                int rb8 = rb + 8 * B_PITCH;
                uint32_t bH1 = pack2h(BsH[rb8], BsH[rb8 + B_PITCH]);
#pragma unroll
                for (int mt = 0; mt < 2; mt++)
                    mma16816h(acc[mt][nt], aH[mt], bH0, bH1);
            }
        }
        __syncthreads();
    }

#pragma unroll
    for (int mt = 0; mt < 2; mt++) {
        int r = r0 + wm * 32 + mt * 16 + g;
#pragma unroll
        for (int nt = 0; nt < 8; nt++) {
            int col = c0 + wn * 64 + nt * 8 + tig * 2;
            float b0 = bias[col], b1 = bias[col + 1];
            float v0 = acc[mt][nt][0] + b0;
            float v1 = acc[mt][nt][1] + b1;
            float v2 = acc[mt][nt][2] + b0;
            float v3 = acc[mt][nt][3] + b1;
            if (RELU) {
                v0 = fmaxf(v0, 0.f); v1 = fmaxf(v1, 0.f);
                v2 = fmaxf(v2, 0.f); v3 = fmaxf(v3, 0.f);
            }
            if (HOUT) {
                __half* C = (__half*)Cv;
                *(__half2*)(C + (size_t)r * ldc + col) =
                    __floats2half2_rn(v0 * oscale, v1 * oscale);
                *(__half2*)(C + (size_t)(r + 8) * ldc + col) =
                    __floats2half2_rn(v2 * oscale, v3 * oscale);
            } else {
                float* C = (float*)Cv;
                *(float2*)(C + (size_t)r * ldc + col)       = make_float2(v0, v1);
                *(float2*)(C + (size_t)(r + 8) * ldc + col) = make_float2(v2, v3);
            }
        }
    }
}

// ---------------------------------------------------------------------------
// Tensor-core flash attention. Block = (b,h): 64 queries, 256 thr = 8 warps.
// QK: warp (mt=w&3) x (nt=w>>2 covering 16 cols); PV: warp rows 16mt, cols 32nt.
// ---------------------------------------------------------------------------
#define QKP 72
#define SSP 36
#define PSP 40

__global__ __launch_bounds__(256) void attn_mma_kernel(
    const __half* __restrict__ Qh,
    const __half* __restrict__ KVh,
    float* __restrict__ Aout)
{
    __shared__ __half Qs[64][QKP];
    __shared__ __half Ks[2][32][QKP];
    __shared__ __half Vs[2][32][QKP];
    __shared__ float  Ss[64][SSP];
    __shared__ __half Ps[64][PSP];
    __shared__ float  m_s[64], l_s[64], f_s[64];

    const int bh = blockIdx.x;
    const int b = bh >> 4, h = bh & 15;
    const __half* Qb = Qh  + (size_t)(b * 64) * 1024 + h * 64;
    const __half* Kb = KVh + (size_t)b * 2048 * 2048 + h * 64;
    const __half* Vb = Kb + 1024;

    const int tid  = threadIdx.x;
    const int lane = tid & 31;
    const int w    = tid >> 5;
    const int g    = lane >> 2;
    const int tig  = lane & 3;
    const int mt   = w & 3;      // m-tile 0..3 (16 rows each)
    const int nt   = w >> 2;     // 0..1

    // load Q (pre-scaled), init softmax state
    for (int i = tid; i < 1024; i += 256) {
        int t = i >> 4, h8 = (i & 15) * 4;
        *(uint2*)&Qs[t][h8] = *(const uint2*)(Qb + (size_t)t * 1024 + h8);
    }
    if (tid < 64) { m_s[tid] = -1e30f; l_s[tid] = 0.f; f_s[tid] = 1.f; }

    float o[4][4];
#pragma unroll
    for (int i = 0; i < 4; i++)
#pragma unroll
        for (int j = 0; j < 4; j++) o[i][j] = 0.f;

    auto load_kv = [&](int st, int s0) {
#pragma unroll
        for (int j = 0; j < 2; j++) {
            int c   = tid + 256 * j;
            int isV = c >> 8;
            int cc  = c & 255;
            int row = cc >> 3;
            int h8  = (cc & 7) * 8;
            const __half* gsrc = (isV ? Vb : Kb) + (size_t)(s0 + row) * 2048 + h8;
            __half* sdst = isV ? &Vs[st][row][h8] : &Ks[st][row][h8];
            cp16(sdst, gsrc);
        }
    };

    load_kv(0, 0);
    asm volatile("cp.async.commit_group;" ::: "memory");

    int buf = 0;
    for (int it = 0; it < 64; it++) {
        if (it < 63) {
            load_kv(buf ^ 1, (it + 1) * 32);
            asm volatile("cp.async.commit_group;" ::: "memory");
            asm volatile("cp.async.wait_group 1;" ::: "memory");
        } else {
            asm volatile("cp.async.wait_group 0;" ::: "memory");
        }
        __syncthreads();

        // ---- QK^T: rows 16mt+{g,g+8}, cols 16nt + 8j + 2tig ----
        float sc[2][4];
#pragma unroll
        for (int j = 0; j < 2; j++)
#pragma unroll
            for (int q = 0; q < 4; q++) sc[j][q] = 0.f;
#pragma unroll
        for (int ks = 0; ks < 4; ks++) {
            uint32_t a[4];
            int cA = 16 * ks + 2 * tig;
            a[0] = *(const uint32_t*)&Qs[16 * mt + g][cA];
            a[1] = *(const uint32_t*)&Qs[16 * mt + g + 8][cA];
            a[2] = *(const uint32_t*)&Qs[16 * mt + g][cA + 8];
            a[3] = *(const uint32_t*)&Qs[16 * mt + g + 8][cA + 8];
#pragma unroll
            for (int j = 0; j < 2; j++) {
                int krow = 16 * nt + 8 * j + g;
                uint32_t b0 = *(const uint32_t*)&Ks[buf][krow][cA];
                uint32_t b1 = *(const uint32_t*)&Ks[buf][krow][cA + 8];
                mma16816h(sc[j], a, b0, b1);
            }
        }
#pragma unroll
        for (int j = 0; j < 2; j++) {
            *(float2*)&Ss[16 * mt + g][16 * nt + 8 * j + 2 * tig]     = make_float2(sc[j][0], sc[j][1]);
            *(float2*)&Ss[16 * mt + g + 8][16 * nt + 8 * j + 2 * tig] = make_float2(sc[j][2], sc[j][3]);
        }
        __syncthreads();

        // ---- online softmax: 4 threads/row, 8 cols each ----
        {
            int row = tid >> 2;
            int c0  = (tid & 3) * 8;
            float4 sa = *(const float4*)&Ss[row][c0];
            float4 sb = *(const float4*)&Ss[row][c0 + 4];
            float cmax = fmaxf(fmaxf(fmaxf(sa.x, sa.y), fmaxf(sa.z, sa.w)),
                               fmaxf(fmaxf(sb.x, sb.y), fmaxf(sb.z, sb.w)));
#pragma unroll
            for (int off = 2; off > 0; off >>= 1)
                cmax = fmaxf(cmax, __shfl_xor_sync(0xffffffffu, cmax, off, 4));
            float mo = m_s[row];
            float mn = fmaxf(mo, cmax);
            float f  = __expf(mo - mn);
            float p0 = __expf(sa.x - mn), p1 = __expf(sa.y - mn);
            float p2 = __expf(sa.z - mn), p3 = __expf(sa.w - mn);
            float p4 = __expf(sb.x - mn), p5 = __expf(sb.y - mn);
            float p6 = __expf(sb.z - mn), p7 = __expf(sb.w - mn);
            float cs = (p0 + p1 + p2 + p3) + (p4 + p5 + p6 + p7);
#pragma unroll
            for (int off = 2; off > 0; off >>= 1)
                cs += __shfl_xor_sync(0xffffffffu, cs, off, 4);
            if ((tid & 3) == 0) {
                m_s[row] = mn;
                l_s[row] = l_s[row] * f + cs;
                f_s[row] = f;
            }
            *(__half2*)&Ps[row][c0]     = __floats2half2_rn(p0, p1);
            *(__half2*)&Ps[row][c0 + 2] = __floats2half2_rn(p2, p3);
            *(__half2*)&Ps[row][c0 + 4] = __floats2half2_rn(p4, p5);
            *(__half2*)&Ps[row][c0 + 6] = __floats2half2_rn(p6, p7);
        }
        __syncthreads();

        // ---- P @ V: rows 16mt+{g,g+8}, cols 32nt + 8j + 2tig ----
        {
            float f0 = f_s[16 * mt + g];
            float f1 = f_s[16 * mt + g + 8];
#pragma unroll
            for (int j = 0; j < 4; j++) {
                o[j][0] *= f0; o[j][1] *= f0;
                o[j][2] *= f1; o[j][3] *= f1;
            }
#pragma unroll
            for (int ks = 0; ks < 2; ks++) {
                uint32_t a[4];
                int cA = 16 * ks + 2 * tig;
                a[0] = *(const uint32_t*)&Ps[16 * mt + g][cA];
                a[1] = *(const uint32_t*)&Ps[16 * mt + g + 8][cA];
                a[2] = *(const uint32_t*)&Ps[16 * mt + g][cA + 8];
                a[3] = *(const uint32_t*)&Ps[16 * mt + g + 8][cA + 8];
#pragma unroll
                for (int j = 0; j < 4; j++) {
                    int n  = 32 * nt + 8 * j + g;
                    int k0 = 16 * ks + 2 * tig;
                    uint32_t b0 = pack2h(__half_as_ushort(Vs[buf][k0][n]),
                                         __half_as_ushort(Vs[buf][k0 + 1][n]));
                    uint32_t b1 = pack2h(__half_as_ushort(Vs[buf][k0 + 8][n]),
                                         __half_as_ushort(Vs[buf][k0 + 9][n]));
                    mma16816h(o[j], a, b0, b1);
                }
            }
        }
        __syncthreads();
        buf ^= 1;
    }

    // ---- write O ----
    {
        int r0g = 16 * mt + g;
        float inv0 = 1.f / l_s[r0g];
        float inv1 = 1.f / l_s[r0g + 8];
        float* Ap = Aout + (size_t)(b * 64) * 1024 + h * 64;
#pragma unroll
        for (int j = 0; j < 4; j++) {
            int col = 32 * nt + 8 * j + 2 * tig;
            *(float2*)(Ap + (size_t)r0g * 1024 + col) =
                make_float2(o[j][0] * inv0, o[j][1] * inv0);
            *(float2*)(Ap + (size_t)(r0g + 8) * 1024 + col) =
                make_float2(o[j][2] * inv1, o[j][3] * inv1);
        }
    }
}

// ---------------------------------------------------------------------------
// out[row] = LayerNorm(pre[row] + res[row]) * g + b   (row length 256)
// ---------------------------------------------------------------------------
__global__ __launch_bounds__(256) void add_ln_kernel(
    const float* __restrict__ pre,
    const float* __restrict__ res,
    const float* __restrict__ g,
    const float* __restrict__ bta,
    float* __restrict__ out)
{
    const int row = blockIdx.x;
    const int t = threadIdx.x;
    const size_t idx = (size_t)row * 256 + t;

    float v = pre[idx] + res[idx];
    float s = v, s2 = v * v;
#pragma unroll
    for (int off = 16; off > 0; off >>= 1) {
        s  += __shfl_xor_sync(0xffffffffu, s,  off);
        s2 += __shfl_xor_sync(0xffffffffu, s2, off);
    }
    __shared__ float rs[8], rs2[8];
    const int w = t >> 5, lane = t & 31;
    if (lane == 0) { rs[w] = s; rs2[w] = s2; }
    __syncthreads();
    if (t < 32) {
        s  = (t < 8) ? rs[t]  : 0.f;
        s2 = (t < 8) ? rs2[t] : 0.f;
#pragma unroll
        for (int off = 4; off > 0; off >>= 1) {
            s  += __shfl_xor_sync(0xffffffffu, s,  off);
            s2 += __shfl_xor_sync(0xffffffffu, s2, off);
        }
        if (t == 0) { rs[0] = s; rs2[0] = s2; }
    }
    __syncthreads();
    float mean = rs[0] * (1.f / 256.f);
    float var  = rs2[0] * (1.f / 256.f) - mean * mean;
    out[idx] = (v - mean) * rsqrtf(var + 1e-5f) * g[t] + bta[t];
}

// ---------------------------------------------------------------------------
extern "C" void kernel_launch(void* const* d_in, const int* in_sizes, int n_in,
                              void* d_out, int out_size)
{
    const float* src  = (const float*)d_in[0];
    const float* tgt  = (const float*)d_in[1];
    const float* Wq   = (const float*)d_in[2];
    const float* bq   = (const float*)d_in[3];
    const float* Wk   = (const float*)d_in[4];
    const float* bk   = (const float*)d_in[5];
    const float* Wv   = (const float*)d_in[6];
    const float* bv   = (const float*)d_in[7];
    const float* Wo   = (const float*)d_in[8];
    const float* bo   = (const float*)d_in[9];
    const float* ln1g = (const float*)d_in[10];
    const float* ln1b = (const float*)d_in[11];
    const float* W1   = (const float*)d_in[12];
    const float* bf1  = (const float*)d_in[13];
    const float* W2   = (const float*)d_in[14];
    const float* bf2  = (const float*)d_in[15];
    const float* ln3g = (const float*)d_in[16];
    const float* ln3b = (const float*)d_in[17];
    float* out = (float*)d_out;

    float *Ap, *F1, *T1, *X1;
    __half *KVh, *Qh;
    ushort_t *srcH, *wkvH;
    cudaGetSymbolAddress((void**)&KVh, g_KVh);
    cudaGetSymbolAddress((void**)&Qh, g_Qh);
    cudaGetSymbolAddress((void**)&Ap, g_A);
    cudaGetSymbolAddress((void**)&F1, g_F1);
    cudaGetSymbolAddress((void**)&T1, g_T1);
    cudaGetSymbolAddress((void**)&X1, g_X1);
    cudaGetSymbolAddress((void**)&srcH, g_srcH);
    cudaGetSymbolAddress((void**)&wkvH, g_wkvH);

    static bool attr_set = false;
    if (!attr_set) {
        cudaFuncSetAttribute(gemm_kv_f16,
                             cudaFuncAttributeMaxDynamicSharedMemorySize, KV_SMEM_BYTES);
        attr_set = true;
    }

    const dim3 blk(256);

    // 1-2: pre-pass conversions
    convert_src_kernel<<<(32768 * 1024 / 4 + 255) / 256, blk>>>(src, srcH, 32768 * 1024 / 4);
    conv_wkv_kernel<<<dim3(64, 32), dim3(32, 8)>>>(Wk, Wv, wkvH);

    // 3: Q projection -> fp16 with 1/8 scale folded
    gemm_tc<false, true><<<dim3(8, 8), blk>>>(tgt, 256, Wq, 1024, bq, Qh, 1024, 256, 0.125f);

    // 4: fused K|V projection (profiled slot)
    gemm_kv_f16<<<dim3(16, 256), blk, KV_SMEM_BYTES>>>(srcH, wkvH, bk, bv, KVh);

    // 5: tensor-core attention (64 queries/block)
    attn_mma_kernel<<<256, blk>>>(Qh, KVh, Ap);

    // 6-7: output projection + residual + LN1
    gemm_tc<false, false><<<dim3(2, 8), blk>>>(Ap, 1024, Wo, 256, bo, T1, 256, 1024, 1.f);
    add_ln_kernel<<<1024, 256>>>(T1, tgt, ln1g, ln1b, X1);

    // 8-9: FFN
    gemm_tc<true, false><<<dim3(8, 8), blk>>>(X1, 256, W1, 1024, bf1, F1, 1024, 256, 1.f);
    gemm_tc<false, false><<<dim3(2, 8), blk>>>(F1, 1024, W2, 256, bf2, T1, 256, 1024, 1.f);

    // 10: residual + LN3 -> output
    add_ln_kernel<<<1024, 256>>>(T1, X1, ln3g, ln3b, out);
}

// round 14
// speedup vs baseline: 1.5192x; 1.5192x over previous
#include <cuda_runtime.h>
#include <cuda_fp16.h>
#include <math.h>
#include <stdint.h>

typedef unsigned short ushort_t;

// ---------------------------------------------------------------------------
// Scratch (device globals; no runtime allocation allowed)
// ---------------------------------------------------------------------------
__device__ __half   g_KVh[(size_t)32768 * 2048];    // [B*S, 2048]: K | V (fp16)
__device__ ushort_t g_srcH[(size_t)32768 * 1024];   // src fp16
__device__ ushort_t g_wkvH[(size_t)2048 * 1024];    // [Wk|Wv]^T fp16 : [n][k]
__device__ __half   g_Qh[(size_t)1024 * 1024];      // Q fp16 (pre-scaled by 1/8)
__device__ float    g_A [(size_t)1024 * 1024];
__device__ float    g_F1[(size_t)1024 * 1024];
__device__ float    g_T1[(size_t)1024 * 256];
__device__ float    g_X1[(size_t)1024 * 256];

// ---------------------------------------------------------------------------
// helpers
// ---------------------------------------------------------------------------
__device__ __forceinline__ void mma16816h(float* c, const uint32_t* a, uint32_t b0, uint32_t b1) {
    asm volatile(
        "mma.sync.aligned.m16n8k16.row.col.f32.f16.f16.f32 "
        "{%0,%1,%2,%3}, {%4,%5,%6,%7}, {%8,%9}, {%0,%1,%2,%3};"
        : "+f"(c[0]), "+f"(c[1]), "+f"(c[2]), "+f"(c[3])
        : "r"(a[0]), "r"(a[1]), "r"(a[2]), "r"(a[3]), "r"(b0), "r"(b1));
}

__device__ __forceinline__ void ldsm4(uint32_t* r, uint32_t saddr) {
    asm volatile(
        "ldmatrix.sync.aligned.m8n8.x4.shared.b16 {%0,%1,%2,%3}, [%4];"
        : "=r"(r[0]), "=r"(r[1]), "=r"(r[2]), "=r"(r[3]) : "r"(saddr));
}

__device__ __forceinline__ void cp16(void* sdst, const void* gsrc) {
    uint32_t s = (uint32_t)__cvta_generic_to_shared(sdst);
    asm volatile("cp.async.cg.shared.global [%0], [%1], 16;" :: "r"(s), "l"(gsrc));
}

__device__ __forceinline__ uint32_t smem_u32(const void* p) {
    return (uint32_t)__cvta_generic_to_shared(p);
}

__device__ __forceinline__ uint32_t pack2h(ushort_t lo, ushort_t hi) {
    return (uint32_t)lo | ((uint32_t)hi << 16);
}

// ---------------------------------------------------------------------------
// pre-pass: fp32 -> fp16 (flat, float4 granularity)
// ---------------------------------------------------------------------------
__global__ __launch_bounds__(256) void convert_src_kernel(
    const float* __restrict__ x, ushort_t* __restrict__ H, int n4)
{
    int i = blockIdx.x * blockDim.x + threadIdx.x;
    if (i >= n4) return;
    float4 v = ((const float4*)x)[i];
    __half2 h0 = __floats2half2_rn(v.x, v.y);
    __half2 h1 = __floats2half2_rn(v.z, v.w);
    ((uint2*)H)[i] = make_uint2(*(uint32_t*)&h0, *(uint32_t*)&h1);
}

// ---------------------------------------------------------------------------
// pre-pass: WT[n][k] = (n<1024 ? Wk[k][n] : Wv[k][n-1024]) -> fp16
// ---------------------------------------------------------------------------
__global__ __launch_bounds__(256) void conv_wkv_kernel(
    const float* __restrict__ Wk, const float* __restrict__ Wv,
    ushort_t* __restrict__ H)
{
    __shared__ float tile[32][33];
    const int n0 = blockIdx.x * 32, k0 = blockIdx.y * 32;
    const float* W = (n0 < 1024) ? Wk : Wv;
    const int nofs = (n0 < 1024) ? n0 : n0 - 1024;
    for (int r = threadIdx.y; r < 32; r += 8)
        tile[r][threadIdx.x] = W[(size_t)(k0 + r) * 1024 + nofs + threadIdx.x];
    __syncthreads();
    for (int r = threadIdx.y; r < 32; r += 8) {
        float v = tile[threadIdx.x][r];
        size_t o = (size_t)(n0 + r) * 1024 + k0 + threadIdx.x;
        H[o] = __half_as_ushort(__float2half_rn(v));
    }
}

// ---------------------------------------------------------------------------
// Fused KV GEMM (R12 config): KVh[32768,2048] = src @ WkvT^T + bias, fp16 io.
// Block tile 128x128, BK=64, 3-stage cp.async pipeline, ldmatrix fragments,
// ONE __syncthreads per stage. 2 CTAs/SM (regs ~110).
// Stage: A 128x64 + B 128x64 halves, pitch 72 -> 36864 B; 3 stages = 110592 B.
// ---------------------------------------------------------------------------
#define TPK 72
#define KV_BOFF (128 * TPK)
#define KV_STAGE_H (2 * 128 * TPK)
#define KV_SMEM_BYTES (3 * KV_STAGE_H * 2)  // 110592

__global__ __launch_bounds__(256) void gemm_kv_f16(
    const ushort_t* __restrict__ srcH,
    const ushort_t* __restrict__ wtH,
    const float* __restrict__ bk, const float* __restrict__ bv,
    __half* __restrict__ C)
{
    extern __shared__ ushort_t smem[];

    const int tid  = threadIdx.x;
    const int lane = tid & 31;
    const int wid  = tid >> 5;
    const int wm   = wid & 3;
    const int wn   = wid >> 2;
    const int g    = lane >> 2;
    const int tig  = lane & 3;

    const int r0 = blockIdx.y * 128;
    const int c0 = blockIdx.x * 128;

    float acc[2][8][4];
#pragma unroll
    for (int mt = 0; mt < 2; mt++)
#pragma unroll
        for (int nt = 0; nt < 8; nt++)
#pragma unroll
            for (int j = 0; j < 4; j++) acc[mt][nt][j] = 0.f;

    // stage loader: 8 cp16 per thread (A 1024 chunks + B 1024 chunks)
    auto load_stage = [&](ushort_t* stg, int kb) {
#pragma unroll
        for (int j = 0; j < 4; j++) {
            int cc  = tid + 256 * j;          // 0..1023
            int row = cc >> 3;
            int c16 = (cc & 7) * 8;
            cp16(&stg[row * TPK + c16], srcH + (size_t)(r0 + row) * 1024 + kb + c16);
        }
#pragma unroll
        for (int j = 0; j < 4; j++) {
            int cc  = tid + 256 * j;
            int row = cc >> 3;
            int c16 = (cc & 7) * 8;
            cp16(&stg[KV_BOFF + row * TPK + c16], wtH + (size_t)(c0 + row) * 1024 + kb + c16);
        }
    };

    const int lrow = lane & 15;
    const int lcol = (lane >> 4) * 8;

    ushort_t* stgs[3] = {smem, smem + KV_STAGE_H, smem + 2 * KV_STAGE_H};

    load_stage(stgs[0], 0);
    asm volatile("cp.async.commit_group;" ::: "memory");
    load_stage(stgs[1], 64);
    asm volatile("cp.async.commit_group;" ::: "memory");

    for (int it = 0; it < 16; it++) {
        if (it < 15) {
            asm volatile("cp.async.wait_group 1;" ::: "memory");
        } else {
            asm volatile("cp.async.wait_group 0;" ::: "memory");
        }
        __syncthreads();

        if (it + 2 < 16) {
            load_stage(stgs[(it + 2) % 3], (it + 2) * 64);
            asm volatile("cp.async.commit_group;" ::: "memory");
        }

        ushort_t* stg = stgs[it % 3];
        const uint32_t aBase0 = smem_u32(&stg[(wm * 32 + lrow) * TPK + lcol]);
        const uint32_t aBase1 = smem_u32(&stg[(wm * 32 + 16 + lrow) * TPK + lcol]);
        const uint32_t bBase  = smem_u32(&stg[KV_BOFF + (wn * 64 + lrow) * TPK + lcol]);

#pragma unroll
        for (int ks = 0; ks < 4; ks++) {
            uint32_t A0[4], A1[4];
            ldsm4(A0, aBase0 + ks * 32);
            ldsm4(A1, aBase1 + ks * 32);
#pragma unroll
            for (int p = 0; p < 4; p++) {
                uint32_t bb[4];
                ldsm4(bb, bBase + (uint32_t)(p * 16 * TPK * 2) + ks * 32);
                mma16816h(acc[0][2 * p],     A0, bb[0], bb[2]);
                mma16816h(acc[1][2 * p],     A1, bb[0], bb[2]);
                mma16816h(acc[0][2 * p + 1], A0, bb[1], bb[3]);
                mma16816h(acc[1][2 * p + 1], A1, bb[1], bb[3]);
            }
        }
    }

    // epilogue: bias add in fp32, store fp16
#pragma unroll
    for (int mt = 0; mt < 2; mt++) {
        int r = r0 + wm * 32 + mt * 16 + g;
#pragma unroll
        for (int nt = 0; nt < 8; nt++) {
            int col = c0 + wn * 64 + nt * 8 + tig * 2;
            float b0 = (col < 1024) ? bk[col] : bv[col - 1024];
            float b1 = (col + 1 < 1024) ? bk[col + 1] : bv[col + 1 - 1024];
            *(__half2*)(C + (size_t)r * 2048 + col) =
                __floats2half2_rn(acc[mt][nt][0] + b0, acc[mt][nt][1] + b1);
            *(__half2*)(C + (size_t)(r + 8) * 2048 + col) =
                __floats2half2_rn(acc[mt][nt][2] + b0, acc[mt][nt][3] + b1);
        }
    }
}

// ---------------------------------------------------------------------------
// Small GEMM: fp32 in, register-prefetch pipelined, single fp16 MMA.
// HOUT: write __half with oscale folded; else fp32 (+optional ReLU).
// ---------------------------------------------------------------------------
#define A_PITCH 40
#define B_PITCH 136

template<bool RELU, bool HOUT>
__global__ __launch_bounds__(256) void gemm_tc(
    const float* __restrict__ A, int lda,
    const float* __restrict__ W, int ldb,
    const float* __restrict__ bias,
    void* __restrict__ Cv, int ldc, int K, float oscale)
{
    __shared__ ushort_t AsH[128 * A_PITCH];
    __shared__ ushort_t BsH[32 * B_PITCH];

    const int tid  = threadIdx.x;
    const int lane = tid & 31;
    const int wid  = tid >> 5;
    const int wm   = wid & 3;
    const int wn   = wid >> 2;
    const int g    = lane >> 2;
    const int tig  = lane & 3;

    const int r0 = blockIdx.y * 128;
    const int c0 = blockIdx.x * 128;

    float acc[2][8][4];
#pragma unroll
    for (int mt = 0; mt < 2; mt++)
#pragma unroll
        for (int nt = 0; nt < 8; nt++)
#pragma unroll
            for (int j = 0; j < 4; j++) acc[mt][nt][j] = 0.f;

    float4 aR[4], bR[4];
#pragma unroll
    for (int i = 0; i < 4; i++) {
        int flat = tid + 256 * i;
        aR[i] = *(const float4*)(A + (size_t)(r0 + (flat >> 3)) * lda + (flat & 7) * 4);
        bR[i] = *(const float4*)(W + (size_t)(flat >> 5) * ldb + c0 + (flat & 31) * 4);
    }

    for (int kb = 0; kb < K; kb += 32) {
#pragma unroll
        for (int i = 0; i < 4; i++) {
            int flat = tid + 256 * i;
            int row = flat >> 3;
            int kc  = (flat & 7) * 4;
            __half2 h0 = __floats2half2_rn(aR[i].x, aR[i].y);
            __half2 h1 = __floats2half2_rn(aR[i].z, aR[i].w);
            *(uint32_t*)&AsH[row * A_PITCH + kc]     = *(uint32_t*)&h0;
            *(uint32_t*)&AsH[row * A_PITCH + kc + 2] = *(uint32_t*)&h1;
            int kr = flat >> 5;
            int nc = (flat & 31) * 4;
            __half2 g0 = __floats2half2_rn(bR[i].x, bR[i].y);
            __half2 g1 = __floats2half2_rn(bR[i].z, bR[i].w);
            *(uint32_t*)&BsH[kr * B_PITCH + nc]     = *(uint32_t*)&g0;
            *(uint32_t*)&BsH[kr * B_PITCH + nc + 2] = *(uint32_t*)&g1;
        }
        __syncthreads();

        if (kb + 32 < K) {
#pragma unroll
            for (int i = 0; i < 4; i++) {
                int flat = tid + 256 * i;
                aR[i] = *(const float4*)(A + (size_t)(r0 + (flat >> 3)) * lda + kb + 32 + (flat & 7) * 4);
                bR[i] = *(const float4*)(W + (size_t)(kb + 32 + (flat >> 5)) * ldb + c0 + (flat & 31) * 4);
            }
        }

#pragma unroll
        for (int ks = 0; ks < 32; ks += 16) {
            uint32_t aH[2][4];
#pragma unroll
            for (int mt = 0; mt < 2; mt++) {
                int rA = wm * 32 + mt * 16 + g;
                int cA = ks + tig * 2;
                aH[mt][0] = *(const uint32_t*)&AsH[rA * A_PITCH + cA];
                aH[mt][1] = *(const uint32_t*)&AsH[(rA + 8) * A_PITCH + cA];
                aH[mt][2] = *(const uint32_t*)&AsH[rA * A_PITCH + cA + 8];
                aH[mt][3] = *(const uint32_t*)&AsH[(rA + 8) * A_PITCH + cA + 8];
            }
#pragma unroll
            for (int nt = 0; nt < 8; nt++) {
                int col = wn * 64 + nt * 8 + g;
                int rb  = (ks + tig * 2) * B_PITCH + col;
                uint32_t bH0 = pack2h(BsH[rb], BsH[rb + B_PITCH]);
                int rb8 = rb + 8 * B_PITCH;
                uint32_t bH1 = pack2h(BsH[rb8], BsH[rb8 + B_PITCH]);
#pragma unroll
                for (int mt = 0; mt < 2; mt++)
                    mma16816h(acc[mt][nt], aH[mt], bH0, bH1);
            }
        }
        __syncthreads();
    }

#pragma unroll
    for (int mt = 0; mt < 2; mt++) {
        int r = r0 + wm * 32 + mt * 16 + g;
#pragma unroll
        for (int nt = 0; nt < 8; nt++) {
            int col = c0 + wn * 64 + nt * 8 + tig * 2;
            float b0 = bias[col], b1 = bias[col + 1];
            float v0 = acc[mt][nt][0] + b0;
            float v1 = acc[mt][nt][1] + b1;
            float v2 = acc[mt][nt][2] + b0;
            float v3 = acc[mt][nt][3] + b1;
            if (RELU) {
                v0 = fmaxf(v0, 0.f); v1 = fmaxf(v1, 0.f);
                v2 = fmaxf(v2, 0.f); v3 = fmaxf(v3, 0.f);
            }
            if (HOUT) {
                __half* C = (__half*)Cv;
                *(__half2*)(C + (size_t)r * ldc + col) =
                    __floats2half2_rn(v0 * oscale, v1 * oscale);
                *(__half2*)(C + (size_t)(r + 8) * ldc + col) =
                    __floats2half2_rn(v2 * oscale, v3 * oscale);
            } else {
                float* C = (float*)Cv;
                *(float2*)(C + (size_t)r * ldc + col)       = make_float2(v0, v1);
                *(float2*)(C + (size_t)(r + 8) * ldc + col) = make_float2(v2, v3);
            }
        }
    }
}

// ---------------------------------------------------------------------------
// Tensor-core flash attention. Block = (b,h): 64 queries, 256 thr = 8 warps.
// ---------------------------------------------------------------------------
#define QKP 72
#define SSP 36
#define PSP 40

__global__ __launch_bounds__(256) void attn_mma_kernel(
    const __half* __restrict__ Qh,
    const __half* __restrict__ KVh,
    float* __restrict__ Aout)
{
    __shared__ __half Qs[64][QKP];
    __shared__ __half Ks[2][32][QKP];
    __shared__ __half Vs[2][32][QKP];
    __shared__ float  Ss[64][SSP];
    __shared__ __half Ps[64][PSP];
    __shared__ float  m_s[64], l_s[64], f_s[64];

    const int bh = blockIdx.x;
    const int b = bh >> 4, h = bh & 15;
    const __half* Qb = Qh  + (size_t)(b * 64) * 1024 + h * 64;
    const __half* Kb = KVh + (size_t)b * 2048 * 2048 + h * 64;
    const __half* Vb = Kb + 1024;

    const int tid  = threadIdx.x;
    const int lane = tid & 31;
    const int w    = tid >> 5;
    const int g    = lane >> 2;
    const int tig  = lane & 3;
    const int mt   = w & 3;
    const int nt   = w >> 2;

    for (int i = tid; i < 1024; i += 256) {
        int t = i >> 4, h8 = (i & 15) * 4;
        *(uint2*)&Qs[t][h8] = *(const uint2*)(Qb + (size_t)t * 1024 + h8);
    }
    if (tid < 64) { m_s[tid] = -1e30f; l_s[tid] = 0.f; f_s[tid] = 1.f; }

    float o[4][4];
#pragma unroll
    for (int i = 0; i < 4; i++)
#pragma unroll
        for (int j = 0; j < 4; j++) o[i][j] = 0.f;

    auto load_kv = [&](int st, int s0) {
#pragma unroll
        for (int j = 0; j < 2; j++) {
            int c   = tid + 256 * j;
            int isV = c >> 8;
            int cc  = c & 255;
            int row = cc >> 3;
            int h8  = (cc & 7) * 8;
            const __half* gsrc = (isV ? Vb : Kb) + (size_t)(s0 + row) * 2048 + h8;
            __half* sdst = isV ? &Vs[st][row][h8] : &Ks[st][row][h8];
            cp16(sdst, gsrc);
        }
    };

    load_kv(0, 0);
    asm volatile("cp.async.commit_group;" ::: "memory");

    int buf = 0;
    for (int it = 0; it < 64; it++) {
        if (it < 63) {
            load_kv(buf ^ 1, (it + 1) * 32);
            asm volatile("cp.async.commit_group;" ::: "memory");
            asm volatile("cp.async.wait_group 1;" ::: "memory");
        } else {
            asm volatile("cp.async.wait_group 0;" ::: "memory");
        }
        __syncthreads();

        // ---- QK^T: rows 16mt+{g,g+8}, cols 16nt + 8j + 2tig ----
        float sc[2][4];
#pragma unroll
        for (int j = 0; j < 2; j++)
#pragma unroll
            for (int q = 0; q < 4; q++) sc[j][q] = 0.f;
#pragma unroll
        for (int ks = 0; ks < 4; ks++) {
            uint32_t a[4];
            int cA = 16 * ks + 2 * tig;
            a[0] = *(const uint32_t*)&Qs[16 * mt + g][cA];
            a[1] = *(const uint32_t*)&Qs[16 * mt + g + 8][cA];
            a[2] = *(const uint32_t*)&Qs[16 * mt + g][cA + 8];
            a[3] = *(const uint32_t*)&Qs[16 * mt + g + 8][cA + 8];
#pragma unroll
            for (int j = 0; j < 2; j++) {
                int krow = 16 * nt + 8 * j + g;
                uint32_t b0 = *(const uint32_t*)&Ks[buf][krow][cA];
                uint32_t b1 = *(const uint32_t*)&Ks[buf][krow][cA + 8];
                mma16816h(sc[j], a, b0, b1);
            }
        }
#pragma unroll
        for (int j = 0; j < 2; j++) {
            *(float2*)&Ss[16 * mt + g][16 * nt + 8 * j + 2 * tig]     = make_float2(sc[j][0], sc[j][1]);
            *(float2*)&Ss[16 * mt + g + 8][16 * nt + 8 * j + 2 * tig] = make_float2(sc[j][2], sc[j][3]);
        }
        __syncthreads();

        // ---- online softmax: 4 threads/row, 8 cols each ----
        {
            int row = tid >> 2;
            int c0  = (tid & 3) * 8;
            float4 sa = *(const float4*)&Ss[row][c0];
            float4 sb = *(const float4*)&Ss[row][c0 + 4];
            float cmax = fmaxf(fmaxf(fmaxf(sa.x, sa.y), fmaxf(sa.z, sa.w)),
                               fmaxf(fmaxf(sb.x, sb.y), fmaxf(sb.z, sb.w)));
#pragma unroll
            for (int off = 2; off > 0; off >>= 1)
                cmax = fmaxf(cmax, __shfl_xor_sync(0xffffffffu, cmax, off, 4));
            float mo = m_s[row];
            float mn = fmaxf(mo, cmax);
            float f  = __expf(mo - mn);
            float p0 = __expf(sa.x - mn), p1 = __expf(sa.y - mn);
            float p2 = __expf(sa.z - mn), p3 = __expf(sa.w - mn);
            float p4 = __expf(sb.x - mn), p5 = __expf(sb.y - mn);
            float p6 = __expf(sb.z - mn), p7 = __expf(sb.w - mn);
            float cs = (p0 + p1 + p2 + p3) + (p4 + p5 + p6 + p7);
#pragma unroll
            for (int off = 2; off > 0; off >>= 1)
                cs += __shfl_xor_sync(0xffffffffu, cs, off, 4);
            if ((tid & 3) == 0) {
                m_s[row] = mn;
                l_s[row] = l_s[row] * f + cs;
                f_s[row] = f;
            }
            *(__half2*)&Ps[row][c0]     = __floats2half2_rn(p0, p1);
            *(__half2*)&Ps[row][c0 + 2] = __floats2half2_rn(p2, p3);
            *(__half2*)&Ps[row][c0 + 4] = __floats2half2_rn(p4, p5);
            *(__half2*)&Ps[row][c0 + 6] = __floats2half2_rn(p6, p7);
        }
        __syncthreads();

        // ---- P @ V: rows 16mt+{g,g+8}, cols 32nt + 8j + 2tig ----
        {
            float f0 = f_s[16 * mt + g];
            float f1 = f_s[16 * mt + g + 8];
#pragma unroll
            for (int j = 0; j < 4; j++) {
                o[j][0] *= f0; o[j][1] *= f0;
                o[j][2] *= f1; o[j][3] *= f1;
            }
#pragma unroll
            for (int ks = 0; ks < 2; ks++) {
                uint32_t a[4];
                int cA = 16 * ks + 2 * tig;
                a[0] = *(const uint32_t*)&Ps[16 * mt + g][cA];
                a[1] = *(const uint32_t*)&Ps[16 * mt + g + 8][cA];
                a[2] = *(const uint32_t*)&Ps[16 * mt + g][cA + 8];
                a[3] = *(const uint32_t*)&Ps[16 * mt + g + 8][cA + 8];
#pragma unroll
                for (int j = 0; j < 4; j++) {
                    int n  = 32 * nt + 8 * j + g;
                    int k0 = 16 * ks + 2 * tig;
                    uint32_t b0 = pack2h(__half_as_ushort(Vs[buf][k0][n]),
                                         __half_as_ushort(Vs[buf][k0 + 1][n]));
                    uint32_t b1 = pack2h(__half_as_ushort(Vs[buf][k0 + 8][n]),
                                         __half_as_ushort(Vs[buf][k0 + 9][n]));
                    mma16816h(o[j], a, b0, b1);
                }
            }
        }
        __syncthreads();
        buf ^= 1;
    }

    // ---- write O ----
    {
        int r0g = 16 * mt + g;
        float inv0 = 1.f / l_s[r0g];
        float inv1 = 1.f / l_s[r0g + 8];
        float* Ap = Aout + (size_t)(b * 64) * 1024 + h * 64;
#pragma unroll
        for (int j = 0; j < 4; j++) {
            int col = 32 * nt + 8 * j + 2 * tig;
            *(float2*)(Ap + (size_t)r0g * 1024 + col) =
                make_float2(o[j][0] * inv0, o[j][1] * inv0);
            *(float2*)(Ap + (size_t)(r0g + 8) * 1024 + col) =
                make_float2(o[j][2] * inv1, o[j][3] * inv1);
        }
    }
}

// ---------------------------------------------------------------------------
// out[row] = LayerNorm(pre[row] + res[row]) * g + b   (row length 256)
// ---------------------------------------------------------------------------
__global__ __launch_bounds__(256) void add_ln_kernel(
    const float* __restrict__ pre,
    const float* __restrict__ res,
    const float* __restrict__ g,
    const float* __restrict__ bta,
    float* __restrict__ out)
{
    const int row = blockIdx.x;
    const int t = threadIdx.x;
    const size_t idx = (size_t)row * 256 + t;

    float v = pre[idx] + res[idx];
    float s = v, s2 = v * v;
#pragma unroll
    for (int off = 16; off > 0; off >>= 1) {
        s  += __shfl_xor_sync(0xffffffffu, s,  off);
        s2 += __shfl_xor_sync(0xffffffffu, s2, off);
    }
    __shared__ float rs[8], rs2[8];
    const int w = t >> 5, lane = t & 31;
    if (lane == 0) { rs[w] = s; rs2[w] = s2; }
    __syncthreads();
    if (t < 32) {
        s  = (t < 8) ? rs[t]  : 0.f;
        s2 = (t < 8) ? rs2[t] : 0.f;
#pragma unroll
        for (int off = 4; off > 0; off >>= 1) {
            s  += __shfl_xor_sync(0xffffffffu, s,  off);
            s2 += __shfl_xor_sync(0xffffffffu, s2, off);
        }
        if (t == 0) { rs[0] = s; rs2[0] = s2; }
    }
    __syncthreads();
    float mean = rs[0] * (1.f / 256.f);
    float var  = rs2[0] * (1.f / 256.f) - mean * mean;
    out[idx] = (v - mean) * rsqrtf(var + 1e-5f) * g[t] + bta[t];
}

// ---------------------------------------------------------------------------
extern "C" void kernel_launch(void* const* d_in, const int* in_sizes, int n_in,
                              void* d_out, int out_size)
{
    const float* src  = (const float*)d_in[0];
    const float* tgt  = (const float*)d_in[1];
    const float* Wq   = (const float*)d_in[2];
    const float* bq   = (const float*)d_in[3];
    const float* Wk   = (const float*)d_in[4];
    const float* bk   = (const float*)d_in[5];
    const float* Wv   = (const float*)d_in[6];
    const float* bv   = (const float*)d_in[7];
    const float* Wo   = (const float*)d_in[8];
    const float* bo   = (const float*)d_in[9];
    const float* ln1g = (const float*)d_in[10];
    const float* ln1b = (const float*)d_in[11];
    const float* W1   = (const float*)d_in[12];
    const float* bf1  = (const float*)d_in[13];
    const float* W2   = (const float*)d_in[14];
    const float* bf2  = (const float*)d_in[15];
    const float* ln3g = (const float*)d_in[16];
    const float* ln3b = (const float*)d_in[17];
    float* out = (float*)d_out;

    float *Ap, *F1, *T1, *X1;
    __half *KVh, *Qh;
    ushort_t *srcH, *wkvH;
    cudaGetSymbolAddress((void**)&KVh, g_KVh);
    cudaGetSymbolAddress((void**)&Qh, g_Qh);
    cudaGetSymbolAddress((void**)&Ap, g_A);
    cudaGetSymbolAddress((void**)&F1, g_F1);
    cudaGetSymbolAddress((void**)&T1, g_T1);
    cudaGetSymbolAddress((void**)&X1, g_X1);
    cudaGetSymbolAddress((void**)&srcH, g_srcH);
    cudaGetSymbolAddress((void**)&wkvH, g_wkvH);

    static bool attr_set = false;
    if (!attr_set) {
        cudaFuncSetAttribute(gemm_kv_f16,
                             cudaFuncAttributeMaxDynamicSharedMemorySize, KV_SMEM_BYTES);
        attr_set = true;
    }

    const dim3 blk(256);

    // 1-2: pre-pass conversions
    convert_src_kernel<<<(32768 * 1024 / 4 + 255) / 256, blk>>>(src, srcH, 32768 * 1024 / 4);
    conv_wkv_kernel<<<dim3(64, 32), dim3(32, 8)>>>(Wk, Wv, wkvH);

    // 3: Q projection -> fp16 with 1/8 scale folded
    gemm_tc<false, true><<<dim3(8, 8), blk>>>(tgt, 256, Wq, 1024, bq, Qh, 1024, 256, 0.125f);

    // 4: fused K|V projection (profiled slot)
    gemm_kv_f16<<<dim3(16, 256), blk, KV_SMEM_BYTES>>>(srcH, wkvH, bk, bv, KVh);

    // 5: tensor-core attention (64 queries/block)
    attn_mma_kernel<<<256, blk>>>(Qh, KVh, Ap);

    // 6-7: output projection + residual + LN1
    gemm_tc<false, false><<<dim3(2, 8), blk>>>(Ap, 1024, Wo, 256, bo, T1, 256, 1024, 1.f);
    add_ln_kernel<<<1024, 256>>>(T1, tgt, ln1g, ln1b, X1);

    // 8-9: FFN
    gemm_tc<true, false><<<dim3(8, 8), blk>>>(X1, 256, W1, 1024, bf1, F1, 1024, 256, 1.f);
    gemm_tc<false, false><<<dim3(2, 8), blk>>>(F1, 1024, W2, 256, bf2, T1, 256, 1024, 1.f);

    // 10: residual + LN3 -> output
    add_ln_kernel<<<1024, 256>>>(T1, X1, ln3g, ln3b, out);
}

// round 15
// speedup vs baseline: 1.5419x; 1.0149x over previous
#include <cuda_runtime.h>
#include <cuda_fp16.h>
#include <math.h>
#include <stdint.h>

typedef unsigned short ushort_t;

// ---------------------------------------------------------------------------
// Scratch (device globals; no runtime allocation allowed)
// ---------------------------------------------------------------------------
__device__ __half   g_KVh[(size_t)32768 * 2048];    // [B*S, 2048]: K | V (fp16)
__device__ ushort_t g_srcH[(size_t)32768 * 1024];   // src fp16
__device__ ushort_t g_wkvH[(size_t)2048 * 1024];    // [Wk|Wv]^T fp16 : [n][k]
__device__ __half   g_Qh[(size_t)1024 * 1024];      // Q fp16 (pre-scaled by 1/8)
__device__ float    g_A [(size_t)1024 * 1024];
__device__ float    g_F1[(size_t)1024 * 1024];
__device__ float    g_T1[(size_t)1024 * 256];
__device__ float    g_X1[(size_t)1024 * 256];

// ---------------------------------------------------------------------------
// helpers
// ---------------------------------------------------------------------------
__device__ __forceinline__ void mma16816h(float* c, const uint32_t* a, uint32_t b0, uint32_t b1) {
    asm volatile(
        "mma.sync.aligned.m16n8k16.row.col.f32.f16.f16.f32 "
        "{%0,%1,%2,%3}, {%4,%5,%6,%7}, {%8,%9}, {%0,%1,%2,%3};"
        : "+f"(c[0]), "+f"(c[1]), "+f"(c[2]), "+f"(c[3])
        : "r"(a[0]), "r"(a[1]), "r"(a[2]), "r"(a[3]), "r"(b0), "r"(b1));
}

__device__ __forceinline__ void ldsm4(uint32_t* r, uint32_t saddr) {
    asm volatile(
        "ldmatrix.sync.aligned.m8n8.x4.shared.b16 {%0,%1,%2,%3}, [%4];"
        : "=r"(r[0]), "=r"(r[1]), "=r"(r[2]), "=r"(r[3]) : "r"(saddr));
}

__device__ __forceinline__ void cp16(void* sdst, const void* gsrc) {
    uint32_t s = (uint32_t)__cvta_generic_to_shared(sdst);
    asm volatile("cp.async.cg.shared.global [%0], [%1], 16;" :: "r"(s), "l"(gsrc));
}

__device__ __forceinline__ uint32_t smem_u32(const void* p) {
    return (uint32_t)__cvta_generic_to_shared(p);
}

__device__ __forceinline__ uint32_t pack2h(ushort_t lo, ushort_t hi) {
    return (uint32_t)lo | ((uint32_t)hi << 16);
}

// ---------------------------------------------------------------------------
// pre-pass: fp32 -> fp16 (flat, float4 granularity)
// ---------------------------------------------------------------------------
__global__ __launch_bounds__(256) void convert_src_kernel(
    const float* __restrict__ x, ushort_t* __restrict__ H, int n4)
{
    int i = blockIdx.x * blockDim.x + threadIdx.x;
    if (i >= n4) return;
    float4 v = ((const float4*)x)[i];
    __half2 h0 = __floats2half2_rn(v.x, v.y);
    __half2 h1 = __floats2half2_rn(v.z, v.w);
    ((uint2*)H)[i] = make_uint2(*(uint32_t*)&h0, *(uint32_t*)&h1);
}

// ---------------------------------------------------------------------------
// pre-pass: WT[n][k] = (n<1024 ? Wk[k][n] : Wv[k][n-1024]) -> fp16
// ---------------------------------------------------------------------------
__global__ __launch_bounds__(256) void conv_wkv_kernel(
    const float* __restrict__ Wk, const float* __restrict__ Wv,
    ushort_t* __restrict__ H)
{
    __shared__ float tile[32][33];
    const int n0 = blockIdx.x * 32, k0 = blockIdx.y * 32;
    const float* W = (n0 < 1024) ? Wk : Wv;
    const int nofs = (n0 < 1024) ? n0 : n0 - 1024;
    for (int r = threadIdx.y; r < 32; r += 8)
        tile[r][threadIdx.x] = W[(size_t)(k0 + r) * 1024 + nofs + threadIdx.x];
    __syncthreads();
    for (int r = threadIdx.y; r < 32; r += 8) {
        float v = tile[threadIdx.x][r];
        size_t o = (size_t)(n0 + r) * 1024 + k0 + threadIdx.x;
        H[o] = __half_as_ushort(__float2half_rn(v));
    }
}

// ---------------------------------------------------------------------------
// Fused KV GEMM: KVh[32768,2048] = src @ WkvT^T + bias, fp16 io.
// Block tile 128x128, BK=64, 3-stage cp.async pipeline, ldmatrix fragments
// batched per ks (all 6 LDSM before the 16-MMA burst). 2 CTAs/SM (cap 128 regs).
// Stage: A 128x64 + B 128x64 halves, pitch 72 -> 36864 B; 3 stages = 110592 B.
// ---------------------------------------------------------------------------
#define TPK 72
#define KV_BOFF (128 * TPK)
#define KV_STAGE_H (2 * 128 * TPK)
#define KV_SMEM_BYTES (3 * KV_STAGE_H * 2)  // 110592

__global__ __launch_bounds__(256, 2) void gemm_kv_f16(
    const ushort_t* __restrict__ srcH,
    const ushort_t* __restrict__ wtH,
    const float* __restrict__ bk, const float* __restrict__ bv,
    __half* __restrict__ C)
{
    extern __shared__ ushort_t smem[];

    const int tid  = threadIdx.x;
    const int lane = tid & 31;
    const int wid  = tid >> 5;
    const int wm   = wid & 3;
    const int wn   = wid >> 2;
    const int g    = lane >> 2;
    const int tig  = lane & 3;

    const int r0 = blockIdx.y * 128;
    const int c0 = blockIdx.x * 128;

    float acc[2][8][4];
#pragma unroll
    for (int mt = 0; mt < 2; mt++)
#pragma unroll
        for (int nt = 0; nt < 8; nt++)
#pragma unroll
            for (int j = 0; j < 4; j++) acc[mt][nt][j] = 0.f;

    // stage loader: 8 cp16 per thread (A 1024 chunks + B 1024 chunks)
    auto load_stage = [&](ushort_t* stg, int kb) {
#pragma unroll
        for (int j = 0; j < 4; j++) {
            int cc  = tid + 256 * j;          // 0..1023
            int row = cc >> 3;
            int c16 = (cc & 7) * 8;
            cp16(&stg[row * TPK + c16], srcH + (size_t)(r0 + row) * 1024 + kb + c16);
        }
#pragma unroll
        for (int j = 0; j < 4; j++) {
            int cc  = tid + 256 * j;
            int row = cc >> 3;
            int c16 = (cc & 7) * 8;
            cp16(&stg[KV_BOFF + row * TPK + c16], wtH + (size_t)(c0 + row) * 1024 + kb + c16);
        }
    };

    const int lrow = lane & 15;
    const int lcol = (lane >> 4) * 8;

    ushort_t* stgs[3] = {smem, smem + KV_STAGE_H, smem + 2 * KV_STAGE_H};

    load_stage(stgs[0], 0);
    asm volatile("cp.async.commit_group;" ::: "memory");
    load_stage(stgs[1], 64);
    asm volatile("cp.async.commit_group;" ::: "memory");

    for (int it = 0; it < 16; it++) {
        if (it < 15) {
            asm volatile("cp.async.wait_group 1;" ::: "memory");
        } else {
            asm volatile("cp.async.wait_group 0;" ::: "memory");
        }
        __syncthreads();

        if (it + 2 < 16) {
            load_stage(stgs[(it + 2) % 3], (it + 2) * 64);
            asm volatile("cp.async.commit_group;" ::: "memory");
        }

        ushort_t* stg = stgs[it % 3];
        const uint32_t aBase0 = smem_u32(&stg[(wm * 32 + lrow) * TPK + lcol]);
        const uint32_t aBase1 = smem_u32(&stg[(wm * 32 + 16 + lrow) * TPK + lcol]);
        const uint32_t bBase  = smem_u32(&stg[KV_BOFF + (wn * 64 + lrow) * TPK + lcol]);

#pragma unroll
        for (int ks = 0; ks < 4; ks++) {
            // batch ALL fragment loads for this ks before the MMA burst
            uint32_t A0[4], A1[4], bb[4][4];
            ldsm4(A0, aBase0 + ks * 32);
            ldsm4(A1, aBase1 + ks * 32);
#pragma unroll
            for (int p = 0; p < 4; p++)
                ldsm4(bb[p], bBase + (uint32_t)(p * 16 * TPK * 2) + ks * 32);

#pragma unroll
            for (int p = 0; p < 4; p++) {
                mma16816h(acc[0][2 * p],     A0, bb[p][0], bb[p][2]);
                mma16816h(acc[1][2 * p],     A1, bb[p][0], bb[p][2]);
                mma16816h(acc[0][2 * p + 1], A0, bb[p][1], bb[p][3]);
                mma16816h(acc[1][2 * p + 1], A1, bb[p][1], bb[p][3]);
            }
        }
    }

    // epilogue: bias add in fp32, store fp16
#pragma unroll
    for (int mt = 0; mt < 2; mt++) {
        int r = r0 + wm * 32 + mt * 16 + g;
#pragma unroll
        for (int nt = 0; nt < 8; nt++) {
            int col = c0 + wn * 64 + nt * 8 + tig * 2;
            float b0 = (col < 1024) ? bk[col] : bv[col - 1024];
            float b1 = (col + 1 < 1024) ? bk[col + 1] : bv[col + 1 - 1024];
            *(__half2*)(C + (size_t)r * 2048 + col) =
                __floats2half2_rn(acc[mt][nt][0] + b0, acc[mt][nt][1] + b1);
            *(__half2*)(C + (size_t)(r + 8) * 2048 + col) =
                __floats2half2_rn(acc[mt][nt][2] + b0, acc[mt][nt][3] + b1);
        }
    }
}

// ---------------------------------------------------------------------------
// Small GEMM: fp32 in, register-prefetch pipelined, single fp16 MMA.
// HOUT: write __half with oscale folded; else fp32 (+optional ReLU).
// ---------------------------------------------------------------------------
#define A_PITCH 40
#define B_PITCH 136

template<bool RELU, bool HOUT>
__global__ __launch_bounds__(256) void gemm_tc(
    const float* __restrict__ A, int lda,
    const float* __restrict__ W, int ldb,
    const float* __restrict__ bias,
    void* __restrict__ Cv, int ldc, int K, float oscale)
{
    __shared__ ushort_t AsH[128 * A_PITCH];
    __shared__ ushort_t BsH[32 * B_PITCH];

    const int tid  = threadIdx.x;
    const int lane = tid & 31;
    const int wid  = tid >> 5;
    const int wm   = wid & 3;
    const int wn   = wid >> 2;
    const int g    = lane >> 2;
    const int tig  = lane & 3;

    const int r0 = blockIdx.y * 128;
    const int c0 = blockIdx.x * 128;

    float acc[2][8][4];
#pragma unroll
    for (int mt = 0; mt < 2; mt++)
#pragma unroll
        for (int nt = 0; nt < 8; nt++)
#pragma unroll
            for (int j = 0; j < 4; j++) acc[mt][nt][j] = 0.f;

    float4 aR[4], bR[4];
#pragma unroll
    for (int i = 0; i < 4; i++) {
        int flat = tid + 256 * i;
        aR[i] = *(const float4*)(A + (size_t)(r0 + (flat >> 3)) * lda + (flat & 7) * 4);
        bR[i] = *(const float4*)(W + (size_t)(flat >> 5) * ldb + c0 + (flat & 31) * 4);
    }

    for (int kb = 0; kb < K; kb += 32) {
#pragma unroll
        for (int i = 0; i < 4; i++) {
            int flat = tid + 256 * i;
            int row = flat >> 3;
            int kc  = (flat & 7) * 4;
            __half2 h0 = __floats2half2_rn(aR[i].x, aR[i].y);
            __half2 h1 = __floats2half2_rn(aR[i].z, aR[i].w);
            *(uint32_t*)&AsH[row * A_PITCH + kc]     = *(uint32_t*)&h0;
            *(uint32_t*)&AsH[row * A_PITCH + kc + 2] = *(uint32_t*)&h1;
            int kr = flat >> 5;
            int nc = (flat & 31) * 4;
            __half2 g0 = __floats2half2_rn(bR[i].x, bR[i].y);
            __half2 g1 = __floats2half2_rn(bR[i].z, bR[i].w);
            *(uint32_t*)&BsH[kr * B_PITCH + nc]     = *(uint32_t*)&g0;
            *(uint32_t*)&BsH[kr * B_PITCH + nc + 2] = *(uint32_t*)&g1;
        }
        __syncthreads();

        if (kb + 32 < K) {
#pragma unroll
            for (int i = 0; i < 4; i++) {
                int flat = tid + 256 * i;
                aR[i] = *(const float4*)(A + (size_t)(r0 + (flat >> 3)) * lda + kb + 32 + (flat & 7) * 4);
                bR[i] = *(const float4*)(W + (size_t)(kb + 32 + (flat >> 5)) * ldb + c0 + (flat & 31) * 4);
            }
        }

#pragma unroll
        for (int ks = 0; ks < 32; ks += 16) {
            uint32_t aH[2][4];
#pragma unroll
            for (int mt = 0; mt < 2; mt++) {
                int rA = wm * 32 + mt * 16 + g;
                int cA = ks + tig * 2;
                aH[mt][0] = *(const uint32_t*)&AsH[rA * A_PITCH + cA];
                aH[mt][1] = *(const uint32_t*)&AsH[(rA + 8) * A_PITCH + cA];
                aH[mt][2] = *(const uint32_t*)&AsH[rA * A_PITCH + cA + 8];
                aH[mt][3] = *(const uint32_t*)&AsH[(rA + 8) * A_PITCH + cA + 8];
            }
#pragma unroll
            for (int nt = 0; nt < 8; nt++) {
                int col = wn * 64 + nt * 8 + g;
                int rb  = (ks + tig * 2) * B_PITCH + col;
                uint32_t bH0 = pack2h(BsH[rb], BsH[rb + B_PITCH]);
                int rb8 = rb + 8 * B_PITCH;
                uint32_t bH1 = pack2h(BsH[rb8], BsH[rb8 + B_PITCH]);
#pragma unroll
                for (int mt = 0; mt < 2; mt++)
                    mma16816h(acc[mt][nt], aH[mt], bH0, bH1);
            }
        }
        __syncthreads();
    }

#pragma unroll
    for (int mt = 0; mt < 2; mt++) {
        int r = r0 + wm * 32 + mt * 16 + g;
#pragma unroll
        for (int nt = 0; nt < 8; nt++) {
            int col = c0 + wn * 64 + nt * 8 + tig * 2;
            float b0 = bias[col], b1 = bias[col + 1];
            float v0 = acc[mt][nt][0] + b0;
            float v1 = acc[mt][nt][1] + b1;
            float v2 = acc[mt][nt][2] + b0;
            float v3 = acc[mt][nt][3] + b1;
            if (RELU) {
                v0 = fmaxf(v0, 0.f); v1 = fmaxf(v1, 0.f);
                v2 = fmaxf(v2, 0.f); v3 = fmaxf(v3, 0.f);
            }
            if (HOUT) {
                __half* C = (__half*)Cv;
                *(__half2*)(C + (size_t)r * ldc + col) =
                    __floats2half2_rn(v0 * oscale, v1 * oscale);
                *(__half2*)(C + (size_t)(r + 8) * ldc + col) =
                    __floats2half2_rn(v2 * oscale, v3 * oscale);
            } else {
                float* C = (float*)Cv;
                *(float2*)(C + (size_t)r * ldc + col)       = make_float2(v0, v1);
                *(float2*)(C + (size_t)(r + 8) * ldc + col) = make_float2(v2, v3);
            }
        }
    }
}

// ---------------------------------------------------------------------------
// Tensor-core flash attention. Block = (b,h): 64 queries, 256 thr = 8 warps.
// ---------------------------------------------------------------------------
#define QKP 72
#define SSP 36
#define PSP 40

__global__ __launch_bounds__(256) void attn_mma_kernel(
    const __half* __restrict__ Qh,
    const __half* __restrict__ KVh,
    float* __restrict__ Aout)
{
    __shared__ __half Qs[64][QKP];
    __shared__ __half Ks[2][32][QKP];
    __shared__ __half Vs[2][32][QKP];
    __shared__ float  Ss[64][SSP];
    __shared__ __half Ps[64][PSP];
    __shared__ float  m_s[64], l_s[64], f_s[64];

    const int bh = blockIdx.x;
    const int b = bh >> 4, h = bh & 15;
    const __half* Qb = Qh  + (size_t)(b * 64) * 1024 + h * 64;
    const __half* Kb = KVh + (size_t)b * 2048 * 2048 + h * 64;
    const __half* Vb = Kb + 1024;

    const int tid  = threadIdx.x;
    const int lane = tid & 31;
    const int w    = tid >> 5;
    const int g    = lane >> 2;
    const int tig  = lane & 3;
    const int mt   = w & 3;
    const int nt   = w >> 2;

    for (int i = tid; i < 1024; i += 256) {
        int t = i >> 4, h8 = (i & 15) * 4;
        *(uint2*)&Qs[t][h8] = *(const uint2*)(Qb + (size_t)t * 1024 + h8);
    }
    if (tid < 64) { m_s[tid] = -1e30f; l_s[tid] = 0.f; f_s[tid] = 1.f; }

    float o[4][4];
#pragma unroll
    for (int i = 0; i < 4; i++)
#pragma unroll
        for (int j = 0; j < 4; j++) o[i][j] = 0.f;

    auto load_kv = [&](int st, int s0) {
#pragma unroll
        for (int j = 0; j < 2; j++) {
            int c   = tid + 256 * j;
            int isV = c >> 8;
            int cc  = c & 255;
            int row = cc >> 3;
            int h8  = (cc & 7) * 8;
            const __half* gsrc = (isV ? Vb : Kb) + (size_t)(s0 + row) * 2048 + h8;
            __half* sdst = isV ? &Vs[st][row][h8] : &Ks[st][row][h8];
            cp16(sdst, gsrc);
        }
    };

    load_kv(0, 0);
    asm volatile("cp.async.commit_group;" ::: "memory");

    int buf = 0;
    for (int it = 0; it < 64; it++) {
        if (it < 63) {
            load_kv(buf ^ 1, (it + 1) * 32);
            asm volatile("cp.async.commit_group;" ::: "memory");
            asm volatile("cp.async.wait_group 1;" ::: "memory");
        } else {
            asm volatile("cp.async.wait_group 0;" ::: "memory");
        }
        __syncthreads();

        // ---- QK^T: rows 16mt+{g,g+8}, cols 16nt + 8j + 2tig ----
        float sc[2][4];
#pragma unroll
        for (int j = 0; j < 2; j++)
#pragma unroll
            for (int q = 0; q < 4; q++) sc[j][q] = 0.f;
#pragma unroll
        for (int ks = 0; ks < 4; ks++) {
            uint32_t a[4];
            int cA = 16 * ks + 2 * tig;
            a[0] = *(const uint32_t*)&Qs[16 * mt + g][cA];
            a[1] = *(const uint32_t*)&Qs[16 * mt + g + 8][cA];
            a[2] = *(const uint32_t*)&Qs[16 * mt + g][cA + 8];
            a[3] = *(const uint32_t*)&Qs[16 * mt + g + 8][cA + 8];
#pragma unroll
            for (int j = 0; j < 2; j++) {
                int krow = 16 * nt + 8 * j + g;
                uint32_t b0 = *(const uint32_t*)&Ks[buf][krow][cA];
                uint32_t b1 = *(const uint32_t*)&Ks[buf][krow][cA + 8];
                mma16816h(sc[j], a, b0, b1);
            }
        }
#pragma unroll
        for (int j = 0; j < 2; j++) {
            *(float2*)&Ss[16 * mt + g][16 * nt + 8 * j + 2 * tig]     = make_float2(sc[j][0], sc[j][1]);
            *(float2*)&Ss[16 * mt + g + 8][16 * nt + 8 * j + 2 * tig] = make_float2(sc[j][2], sc[j][3]);
        }
        __syncthreads();

        // ---- online softmax: 4 threads/row, 8 cols each ----
        {
            int row = tid >> 2;
            int c0  = (tid & 3) * 8;
            float4 sa = *(const float4*)&Ss[row][c0];
            float4 sb = *(const float4*)&Ss[row][c0 + 4];
            float cmax = fmaxf(fmaxf(fmaxf(sa.x, sa.y), fmaxf(sa.z, sa.w)),
                               fmaxf(fmaxf(sb.x, sb.y), fmaxf(sb.z, sb.w)));
#pragma unroll
            for (int off = 2; off > 0; off >>= 1)
                cmax = fmaxf(cmax, __shfl_xor_sync(0xffffffffu, cmax, off, 4));
            float mo = m_s[row];
            float mn = fmaxf(mo, cmax);
            float f  = __expf(mo - mn);
            float p0 = __expf(sa.x - mn), p1 = __expf(sa.y - mn);
            float p2 = __expf(sa.z - mn), p3 = __expf(sa.w - mn);
            float p4 = __expf(sb.x - mn), p5 = __expf(sb.y - mn);
            float p6 = __expf(sb.z - mn), p7 = __expf(sb.w - mn);
            float cs = (p0 + p1 + p2 + p3) + (p4 + p5 + p6 + p7);
#pragma unroll
            for (int off = 2; off > 0; off >>= 1)
                cs += __shfl_xor_sync(0xffffffffu, cs, off, 4);
            if ((tid & 3) == 0) {
                m_s[row] = mn;
                l_s[row] = l_s[row] * f + cs;
                f_s[row] = f;
            }
            *(__half2*)&Ps[row][c0]     = __floats2half2_rn(p0, p1);
            *(__half2*)&Ps[row][c0 + 2] = __floats2half2_rn(p2, p3);
            *(__half2*)&Ps[row][c0 + 4] = __floats2half2_rn(p4, p5);
            *(__half2*)&Ps[row][c0 + 6] = __floats2half2_rn(p6, p7);
        }
        __syncthreads();

        // ---- P @ V: rows 16mt+{g,g+8}, cols 32nt + 8j + 2tig ----
        {
            float f0 = f_s[16 * mt + g];
            float f1 = f_s[16 * mt + g + 8];
#pragma unroll
            for (int j = 0; j < 4; j++) {
                o[j][0] *= f0; o[j][1] *= f0;
                o[j][2] *= f1; o[j][3] *= f1;
            }
#pragma unroll
            for (int ks = 0; ks < 2; ks++) {
                uint32_t a[4];
                int cA = 16 * ks + 2 * tig;
                a[0] = *(const uint32_t*)&Ps[16 * mt + g][cA];
                a[1] = *(const uint32_t*)&Ps[16 * mt + g + 8][cA];
                a[2] = *(const uint32_t*)&Ps[16 * mt + g][cA + 8];
                a[3] = *(const uint32_t*)&Ps[16 * mt + g + 8][cA + 8];
#pragma unroll
                for (int j = 0; j < 4; j++) {
                    int n  = 32 * nt + 8 * j + g;
                    int k0 = 16 * ks + 2 * tig;
                    uint32_t b0 = pack2h(__half_as_ushort(Vs[buf][k0][n]),
                                         __half_as_ushort(Vs[buf][k0 + 1][n]));
                    uint32_t b1 = pack2h(__half_as_ushort(Vs[buf][k0 + 8][n]),
                                         __half_as_ushort(Vs[buf][k0 + 9][n]));
                    mma16816h(o[j], a, b0, b1);
                }
            }
        }
        __syncthreads();
        buf ^= 1;
    }

    // ---- write O ----
    {
        int r0g = 16 * mt + g;
        float inv0 = 1.f / l_s[r0g];
        float inv1 = 1.f / l_s[r0g + 8];
        float* Ap = Aout + (size_t)(b * 64) * 1024 + h * 64;
#pragma unroll
        for (int j = 0; j < 4; j++) {
            int col = 32 * nt + 8 * j + 2 * tig;
            *(float2*)(Ap + (size_t)r0g * 1024 + col) =
                make_float2(o[j][0] * inv0, o[j][1] * inv0);
            *(float2*)(Ap + (size_t)(r0g + 8) * 1024 + col) =
                make_float2(o[j][2] * inv1, o[j][3] * inv1);
        }
    }
}

// ---------------------------------------------------------------------------
// out[row] = LayerNorm(pre[row] + res[row]) * g + b   (row length 256)
// ---------------------------------------------------------------------------
__global__ __launch_bounds__(256) void add_ln_kernel(
    const float* __restrict__ pre,
    const float* __restrict__ res,
    const float* __restrict__ g,
    const float* __restrict__ bta,
    float* __restrict__ out)
{
    const int row = blockIdx.x;
    const int t = threadIdx.x;
    const size_t idx = (size_t)row * 256 + t;

    float v = pre[idx] + res[idx];
    float s = v, s2 = v * v;
#pragma unroll
    for (int off = 16; off > 0; off >>= 1) {
        s  += __shfl_xor_sync(0xffffffffu, s,  off);
        s2 += __shfl_xor_sync(0xffffffffu, s2, off);
    }
    __shared__ float rs[8], rs2[8];
    const int w = t >> 5, lane = t & 31;
    if (lane == 0) { rs[w] = s; rs2[w] = s2; }
    __syncthreads();
    if (t < 32) {
        s  = (t < 8) ? rs[t]  : 0.f;
        s2 = (t < 8) ? rs2[t] : 0.f;
#pragma unroll
        for (int off = 4; off > 0; off >>= 1) {
            s  += __shfl_xor_sync(0xffffffffu, s,  off);
            s2 += __shfl_xor_sync(0xffffffffu, s2, off);
        }
        if (t == 0) { rs[0] = s; rs2[0] = s2; }
    }
    __syncthreads();
    float mean = rs[0] * (1.f / 256.f);
    float var  = rs2[0] * (1.f / 256.f) - mean * mean;
    out[idx] = (v - mean) * rsqrtf(var + 1e-5f) * g[t] + bta[t];
}

// ---------------------------------------------------------------------------
extern "C" void kernel_launch(void* const* d_in, const int* in_sizes, int n_in,
                              void* d_out, int out_size)
{
    const float* src  = (const float*)d_in[0];
    const float* tgt  = (const float*)d_in[1];
    const float* Wq   = (const float*)d_in[2];
    const float* bq   = (const float*)d_in[3];
    const float* Wk   = (const float*)d_in[4];
    const float* bk   = (const float*)d_in[5];
    const float* Wv   = (const float*)d_in[6];
    const float* bv   = (const float*)d_in[7];
    const float* Wo   = (const float*)d_in[8];
    const float* bo   = (const float*)d_in[9];
    const float* ln1g = (const float*)d_in[10];
    const float* ln1b = (const float*)d_in[11];
    const float* W1   = (const float*)d_in[12];
    const float* bf1  = (const float*)d_in[13];
    const float* W2   = (const float*)d_in[14];
    const float* bf2  = (const float*)d_in[15];
    const float* ln3g = (const float*)d_in[16];
    const float* ln3b = (const float*)d_in[17];
    float* out = (float*)d_out;

    float *Ap, *F1, *T1, *X1;
    __half *KVh, *Qh;
    ushort_t *srcH, *wkvH;
    cudaGetSymbolAddress((void**)&KVh, g_KVh);
    cudaGetSymbolAddress((void**)&Qh, g_Qh);
    cudaGetSymbolAddress((void**)&Ap, g_A);
    cudaGetSymbolAddress((void**)&F1, g_F1);
    cudaGetSymbolAddress((void**)&T1, g_T1);
    cudaGetSymbolAddress((void**)&X1, g_X1);
    cudaGetSymbolAddress((void**)&srcH, g_srcH);
    cudaGetSymbolAddress((void**)&wkvH, g_wkvH);

    static bool attr_set = false;
    if (!attr_set) {
        cudaFuncSetAttribute(gemm_kv_f16,
                             cudaFuncAttributeMaxDynamicSharedMemorySize, KV_SMEM_BYTES);
        attr_set = true;
    }

    const dim3 blk(256);

    // 1-2: pre-pass conversions
    convert_src_kernel<<<(32768 * 1024 / 4 + 255) / 256, blk>>>(src, srcH, 32768 * 1024 / 4);
    conv_wkv_kernel<<<dim3(64, 32), dim3(32, 8)>>>(Wk, Wv, wkvH);

    // 3: Q projection -> fp16 with 1/8 scale folded
    gemm_tc<false, true><<<dim3(8, 8), blk>>>(tgt, 256, Wq, 1024, bq, Qh, 1024, 256, 0.125f);

    // 4: fused K|V projection (profiled slot)
    gemm_kv_f16<<<dim3(16, 256), blk, KV_SMEM_BYTES>>>(srcH, wkvH, bk, bv, KVh);

    // 5: tensor-core attention (64 queries/block)
    attn_mma_kernel<<<256, blk>>>(Qh, KVh, Ap);

    // 6-7: output projection + residual + LN1
    gemm_tc<false, false><<<dim3(2, 8), blk>>>(Ap, 1024, Wo, 256, bo, T1, 256, 1024, 1.f);
    add_ln_kernel<<<1024, 256>>>(T1, tgt, ln1g, ln1b, X1);

    // 8-9: FFN
    gemm_tc<true, false><<<dim3(8, 8), blk>>>(X1, 256, W1, 1024, bf1, F1, 1024, 256, 1.f);
    gemm_tc<false, false><<<dim3(2, 8), blk>>>(F1, 1024, W2, 256, bf2, T1, 256, 1024, 1.f);

    // 10: residual + LN3 -> output
    add_ln_kernel<<<1024, 256>>>(T1, X1, ln3g, ln3b, out);
}

// round 17
// speedup vs baseline: 1.6495x; 1.0698x over previous
#include <cuda_runtime.h>
#include <cuda_fp16.h>
#include <math.h>
#include <stdint.h>

typedef unsigned short ushort_t;

// ---------------------------------------------------------------------------
// Scratch (device globals; no runtime allocation allowed)
// ---------------------------------------------------------------------------
__device__ __half   g_KVh[(size_t)32768 * 2048];    // [B*S, 2048]: K | V (fp16)
__device__ ushort_t g_srcH[(size_t)32768 * 1024];   // src fp16
__device__ ushort_t g_wkvH[(size_t)2048 * 1024];    // [Wk|Wv]^T fp16 : [n][k]
__device__ __half   g_Qh[(size_t)1024 * 1024];      // Q fp16 (pre-scaled by 1/8)
__device__ float    g_A [(size_t)1024 * 1024];      // attn out; later W2 split-K partials
__device__ float    g_F1[(size_t)1024 * 1024];      // Wo split-K partials; later FFN hidden
__device__ float    g_X1[(size_t)1024 * 256];

// ---------------------------------------------------------------------------
// helpers
// ---------------------------------------------------------------------------
__device__ __forceinline__ void mma16816h(float* c, const uint32_t* a, uint32_t b0, uint32_t b1) {
    asm volatile(
        "mma.sync.aligned.m16n8k16.row.col.f32.f16.f16.f32 "
        "{%0,%1,%2,%3}, {%4,%5,%6,%7}, {%8,%9}, {%0,%1,%2,%3};"
        : "+f"(c[0]), "+f"(c[1]), "+f"(c[2]), "+f"(c[3])
        : "r"(a[0]), "r"(a[1]), "r"(a[2]), "r"(a[3]), "r"(b0), "r"(b1));
}

__device__ __forceinline__ void ldsm4(uint32_t* r, uint32_t saddr) {
    asm volatile(
        "ldmatrix.sync.aligned.m8n8.x4.shared.b16 {%0,%1,%2,%3}, [%4];"
        : "=r"(r[0]), "=r"(r[1]), "=r"(r[2]), "=r"(r[3]) : "r"(saddr));
}

__device__ __forceinline__ void cp16(void* sdst, const void* gsrc) {
    uint32_t s = (uint32_t)__cvta_generic_to_shared(sdst);
    asm volatile("cp.async.cg.shared.global [%0], [%1], 16;" :: "r"(s), "l"(gsrc));
}

__device__ __forceinline__ uint32_t smem_u32(const void* p) {
    return (uint32_t)__cvta_generic_to_shared(p);
}

__device__ __forceinline__ uint32_t pack2h(ushort_t lo, ushort_t hi) {
    return (uint32_t)lo | ((uint32_t)hi << 16);
}

// ---------------------------------------------------------------------------
// pre-pass: fp32 -> fp16 (flat, float4 granularity)
// ---------------------------------------------------------------------------
__global__ __launch_bounds__(256) void convert_src_kernel(
    const float* __restrict__ x, ushort_t* __restrict__ H, int n4)
{
    int i = blockIdx.x * blockDim.x + threadIdx.x;
    if (i >= n4) return;
    float4 v = ((const float4*)x)[i];
    __half2 h0 = __floats2half2_rn(v.x, v.y);
    __half2 h1 = __floats2half2_rn(v.z, v.w);
    ((uint2*)H)[i] = make_uint2(*(uint32_t*)&h0, *(uint32_t*)&h1);
}

// ---------------------------------------------------------------------------
// pre-pass: WT[n][k] = (n<1024 ? Wk[k][n] : Wv[k][n-1024]) -> fp16
// ---------------------------------------------------------------------------
__global__ __launch_bounds__(256) void conv_wkv_kernel(
    const float* __restrict__ Wk, const float* __restrict__ Wv,
    ushort_t* __restrict__ H)
{
    __shared__ float tile[32][33];
    const int n0 = blockIdx.x * 32, k0 = blockIdx.y * 32;
    const float* W = (n0 < 1024) ? Wk : Wv;
    const int nofs = (n0 < 1024) ? n0 : n0 - 1024;
    for (int r = threadIdx.y; r < 32; r += 8)
        tile[r][threadIdx.x] = W[(size_t)(k0 + r) * 1024 + nofs + threadIdx.x];
    __syncthreads();
    for (int r = threadIdx.y; r < 32; r += 8) {
        float v = tile[threadIdx.x][r];
        size_t o = (size_t)(n0 + r) * 1024 + k0 + threadIdx.x;
        H[o] = __half_as_ushort(__float2half_rn(v));
    }
}

// ---------------------------------------------------------------------------
// Fused KV GEMM (at issue floor — unchanged from R15).
// Block tile 128x128, BK=64, 3-stage cp.async, batched ldmatrix, 2 CTAs/SM.
// ---------------------------------------------------------------------------
#define TPK 72
#define KV_BOFF (128 * TPK)
#define KV_STAGE_H (2 * 128 * TPK)
#define KV_SMEM_BYTES (3 * KV_STAGE_H * 2)  // 110592

__global__ __launch_bounds__(256, 2) void gemm_kv_f16(
    const ushort_t* __restrict__ srcH,
    const ushort_t* __restrict__ wtH,
    const float* __restrict__ bk, const float* __restrict__ bv,
    __half* __restrict__ C)
{
    extern __shared__ ushort_t smem[];

    const int tid  = threadIdx.x;
    const int lane = tid & 31;
    const int wid  = tid >> 5;
    const int wm   = wid & 3;
    const int wn   = wid >> 2;
    const int g    = lane >> 2;
    const int tig  = lane & 3;

    const int r0 = blockIdx.y * 128;
    const int c0 = blockIdx.x * 128;

    float acc[2][8][4];
#pragma unroll
    for (int mt = 0; mt < 2; mt++)
#pragma unroll
        for (int nt = 0; nt < 8; nt++)
#pragma unroll
            for (int j = 0; j < 4; j++) acc[mt][nt][j] = 0.f;

    auto load_stage = [&](ushort_t* stg, int kb) {
#pragma unroll
        for (int j = 0; j < 4; j++) {
            int cc  = tid + 256 * j;
            int row = cc >> 3;
            int c16 = (cc & 7) * 8;
            cp16(&stg[row * TPK + c16], srcH + (size_t)(r0 + row) * 1024 + kb + c16);
        }
#pragma unroll
        for (int j = 0; j < 4; j++) {
            int cc  = tid + 256 * j;
            int row = cc >> 3;
            int c16 = (cc & 7) * 8;
            cp16(&stg[KV_BOFF + row * TPK + c16], wtH + (size_t)(c0 + row) * 1024 + kb + c16);
        }
    };

    const int lrow = lane & 15;
    const int lcol = (lane >> 4) * 8;

    ushort_t* stgs[3] = {smem, smem + KV_STAGE_H, smem + 2 * KV_STAGE_H};

    load_stage(stgs[0], 0);
    asm volatile("cp.async.commit_group;" ::: "memory");
    load_stage(stgs[1], 64);
    asm volatile("cp.async.commit_group;" ::: "memory");

    for (int it = 0; it < 16; it++) {
        if (it < 15) {
            asm volatile("cp.async.wait_group 1;" ::: "memory");
        } else {
            asm volatile("cp.async.wait_group 0;" ::: "memory");
        }
        __syncthreads();

        if (it + 2 < 16) {
            load_stage(stgs[(it + 2) % 3], (it + 2) * 64);
            asm volatile("cp.async.commit_group;" ::: "memory");
        }

        ushort_t* stg = stgs[it % 3];
        const uint32_t aBase0 = smem_u32(&stg[(wm * 32 + lrow) * TPK + lcol]);
        const uint32_t aBase1 = smem_u32(&stg[(wm * 32 + 16 + lrow) * TPK + lcol]);
        const uint32_t bBase  = smem_u32(&stg[KV_BOFF + (wn * 64 + lrow) * TPK + lcol]);

#pragma unroll
        for (int ks = 0; ks < 4; ks++) {
            uint32_t A0[4], A1[4], bb[4][4];
            ldsm4(A0, aBase0 + ks * 32);
            ldsm4(A1, aBase1 + ks * 32);
#pragma unroll
            for (int p = 0; p < 4; p++)
                ldsm4(bb[p], bBase + (uint32_t)(p * 16 * TPK * 2) + ks * 32);

#pragma unroll
            for (int p = 0; p < 4; p++) {
                mma16816h(acc[0][2 * p],     A0, bb[p][0], bb[p][2]);
                mma16816h(acc[1][2 * p],     A1, bb[p][0], bb[p][2]);
                mma16816h(acc[0][2 * p + 1], A0, bb[p][1], bb[p][3]);
                mma16816h(acc[1][2 * p + 1], A1, bb[p][1], bb[p][3]);
            }
        }
    }

    // epilogue: bias add in fp32, store fp16
#pragma unroll
    for (int mt = 0; mt < 2; mt++) {
        int r = r0 + wm * 32 + mt * 16 + g;
#pragma unroll
        for (int nt = 0; nt < 8; nt++) {
            int col = c0 + wn * 64 + nt * 8 + tig * 2;
            float b0 = (col < 1024) ? bk[col] : bv[col - 1024];
            float b1 = (col + 1 < 1024) ? bk[col + 1] : bv[col + 1 - 1024];
            *(__half2*)(C + (size_t)r * 2048 + col) =
                __floats2half2_rn(acc[mt][nt][0] + b0, acc[mt][nt][1] + b1);
            *(__half2*)(C + (size_t)(r + 8) * 2048 + col) =
                __floats2half2_rn(acc[mt][nt][2] + b0, acc[mt][nt][3] + b1);
        }
    }
}

// ---------------------------------------------------------------------------
// Small GEMM: fp32 in, register-prefetch pipelined, single fp16 MMA.
// HOUT: write __half with oscale folded; else fp32 (+optional ReLU).
// ---------------------------------------------------------------------------
#define A_PITCH 40
#define B_PITCH 136

template<bool RELU, bool HOUT>
__global__ __launch_bounds__(256) void gemm_tc(
    const float* __restrict__ A, int lda,
    const float* __restrict__ W, int ldb,
    const float* __restrict__ bias,
    void* __restrict__ Cv, int ldc, int K, float oscale)
{
    __shared__ ushort_t AsH[128 * A_PITCH];
    __shared__ ushort_t BsH[32 * B_PITCH];

    const int tid  = threadIdx.x;
    const int lane = tid & 31;
    const int wid  = tid >> 5;
    const int wm   = wid & 3;
    const int wn   = wid >> 2;
    const int g    = lane >> 2;
    const int tig  = lane & 3;

    const int r0 = blockIdx.y * 128;
    const int c0 = blockIdx.x * 128;

    float acc[2][8][4];
#pragma unroll
    for (int mt = 0; mt < 2; mt++)
#pragma unroll
        for (int nt = 0; nt < 8; nt++)
#pragma unroll
            for (int j = 0; j < 4; j++) acc[mt][nt][j] = 0.f;

    float4 aR[4], bR[4];
#pragma unroll
    for (int i = 0; i < 4; i++) {
        int flat = tid + 256 * i;
        aR[i] = *(const float4*)(A + (size_t)(r0 + (flat >> 3)) * lda + (flat & 7) * 4);
        bR[i] = *(const float4*)(W + (size_t)(flat >> 5) * ldb + c0 + (flat & 31) * 4);
    }

    for (int kb = 0; kb < K; kb += 32) {
#pragma unroll
        for (int i = 0; i < 4; i++) {
            int flat = tid + 256 * i;
            int row = flat >> 3;
            int kc  = (flat & 7) * 4;
            __half2 h0 = __floats2half2_rn(aR[i].x, aR[i].y);
            __half2 h1 = __floats2half2_rn(aR[i].z, aR[i].w);
            *(uint32_t*)&AsH[row * A_PITCH + kc]     = *(uint32_t*)&h0;
            *(uint32_t*)&AsH[row * A_PITCH + kc + 2] = *(uint32_t*)&h1;
            int kr = flat >> 5;
            int nc = (flat & 31) * 4;
            __half2 g0 = __floats2half2_rn(bR[i].x, bR[i].y);
            __half2 g1 = __floats2half2_rn(bR[i].z, bR[i].w);
            *(uint32_t*)&BsH[kr * B_PITCH + nc]     = *(uint32_t*)&g0;
            *(uint32_t*)&BsH[kr * B_PITCH + nc + 2] = *(uint32_t*)&g1;
        }
        __syncthreads();

        if (kb + 32 < K) {
#pragma unroll
            for (int i = 0; i < 4; i++) {
                int flat = tid + 256 * i;
                aR[i] = *(const float4*)(A + (size_t)(r0 + (flat >> 3)) * lda + kb + 32 + (flat & 7) * 4);
                bR[i] = *(const float4*)(W + (size_t)(kb + 32 + (flat >> 5)) * ldb + c0 + (flat & 31) * 4);
            }
        }

#pragma unroll
        for (int ks = 0; ks < 32; ks += 16) {
            uint32_t aH[2][4];
#pragma unroll
            for (int mt = 0; mt < 2; mt++) {
                int rA = wm * 32 + mt * 16 + g;
                int cA = ks + tig * 2;
                aH[mt][0] = *(const uint32_t*)&AsH[rA * A_PITCH + cA];
                aH[mt][1] = *(const uint32_t*)&AsH[(rA + 8) * A_PITCH + cA];
                aH[mt][2] = *(const uint32_t*)&AsH[rA * A_PITCH + cA + 8];
                aH[mt][3] = *(const uint32_t*)&AsH[(rA + 8) * A_PITCH + cA + 8];
            }
#pragma unroll
            for (int nt = 0; nt < 8; nt++) {
                int col = wn * 64 + nt * 8 + g;
                int rb  = (ks + tig * 2) * B_PITCH + col;
                uint32_t bH0 = pack2h(BsH[rb], BsH[rb + B_PITCH]);
                int rb8 = rb + 8 * B_PITCH;
                uint32_t bH1 = pack2h(BsH[rb8], BsH[rb8 + B_PITCH]);
#pragma unroll
                for (int mt = 0; mt < 2; mt++)
                    mma16816h(acc[mt][nt], aH[mt], bH0, bH1);
            }
        }
        __syncthreads();
    }

#pragma unroll
    for (int mt = 0; mt < 2; mt++) {
        int r = r0 + wm * 32 + mt * 16 + g;
#pragma unroll
        for (int nt = 0; nt < 8; nt++) {
            int col = c0 + wn * 64 + nt * 8 + tig * 2;
            float b0 = bias[col], b1 = bias[col + 1];
            float v0 = acc[mt][nt][0] + b0;
            float v1 = acc[mt][nt][1] + b1;
            float v2 = acc[mt][nt][2] + b0;
            float v3 = acc[mt][nt][3] + b1;
            if (RELU) {
                v0 = fmaxf(v0, 0.f); v1 = fmaxf(v1, 0.f);
                v2 = fmaxf(v2, 0.f); v3 = fmaxf(v3, 0.f);
            }
            if (HOUT) {
                __half* C = (__half*)Cv;
                *(__half2*)(C + (size_t)r * ldc + col) =
                    __floats2half2_rn(v0 * oscale, v1 * oscale);
                *(__half2*)(C + (size_t)(r + 8) * ldc + col) =
                    __floats2half2_rn(v2 * oscale, v3 * oscale);
            } else {
                float* C = (float*)Cv;
                *(float2*)(C + (size_t)r * ldc + col)       = make_float2(v0, v1);
                *(float2*)(C + (size_t)(r + 8) * ldc + col) = make_float2(v2, v3);
            }
        }
    }
}

// ---------------------------------------------------------------------------
// Split-K GEMM (x4): partial C[z] = A[:, kz:kz+K/4] @ W[kz:kz+K/4, :]
// No bias/activation; fp32 partial tiles stored at Cpart + z*splitStride.
// grid (N/128, M/128, 4).
// ---------------------------------------------------------------------------
__global__ __launch_bounds__(256) void gemm_splitk4(
    const float* __restrict__ A, int lda,
    const float* __restrict__ W, int ldb,
    float* __restrict__ Cpart, int ldc, int K, size_t splitStride)
{
    __shared__ ushort_t AsH[128 * A_PITCH];
    __shared__ ushort_t BsH[32 * B_PITCH];

    const int tid  = threadIdx.x;
    const int lane = tid & 31;
    const int wid  = tid >> 5;
    const int wm   = wid & 3;
    const int wn   = wid >> 2;
    const int g    = lane >> 2;
    const int tig  = lane & 3;

    const int r0 = blockIdx.y * 128;
    const int c0 = blockIdx.x * 128;
    const int Kp = K >> 2;
    const int kz = blockIdx.z * Kp;
    float* C = Cpart + (size_t)blockIdx.z * splitStride;

    float acc[2][8][4];
#pragma unroll
    for (int mt = 0; mt < 2; mt++)
#pragma unroll
        for (int nt = 0; nt < 8; nt++)
#pragma unroll
            for (int j = 0; j < 4; j++) acc[mt][nt][j] = 0.f;

    float4 aR[4], bR[4];
#pragma unroll
    for (int i = 0; i < 4; i++) {
        int flat = tid + 256 * i;
        aR[i] = *(const float4*)(A + (size_t)(r0 + (flat >> 3)) * lda + kz + (flat & 7) * 4);
        bR[i] = *(const float4*)(W + (size_t)(kz + (flat >> 5)) * ldb + c0 + (flat & 31) * 4);
    }

    for (int kb = kz; kb < kz + Kp; kb += 32) {
#pragma unroll
        for (int i = 0; i < 4; i++) {
            int flat = tid + 256 * i;
            int row = flat >> 3;
            int kc  = (flat & 7) * 4;
            __half2 h0 = __floats2half2_rn(aR[i].x, aR[i].y);
            __half2 h1 = __floats2half2_rn(aR[i].z, aR[i].w);
            *(uint32_t*)&AsH[row * A_PITCH + kc]     = *(uint32_t*)&h0;
            *(uint32_t*)&AsH[row * A_PITCH + kc + 2] = *(uint32_t*)&h1;
            int kr = flat >> 5;
            int nc = (flat & 31) * 4;
            __half2 g0 = __floats2half2_rn(bR[i].x, bR[i].y);
            __half2 g1 = __floats2half2_rn(bR[i].z, bR[i].w);
            *(uint32_t*)&BsH[kr * B_PITCH + nc]     = *(uint32_t*)&g0;
            *(uint32_t*)&BsH[kr * B_PITCH + nc + 2] = *(uint32_t*)&g1;
        }
        __syncthreads();

        if (kb + 32 < kz + Kp) {
#pragma unroll
            for (int i = 0; i < 4; i++) {
                int flat = tid + 256 * i;
                aR[i] = *(const float4*)(A + (size_t)(r0 + (flat >> 3)) * lda + kb + 32 + (flat & 7) * 4);
                bR[i] = *(const float4*)(W + (size_t)(kb + 32 + (flat >> 5)) * ldb + c0 + (flat & 31) * 4);
            }
        }

#pragma unroll
        for (int ks = 0; ks < 32; ks += 16) {
            uint32_t aH[2][4];
#pragma unroll
            for (int mt = 0; mt < 2; mt++) {
                int rA = wm * 32 + mt * 16 + g;
                int cA = ks + tig * 2;
                aH[mt][0] = *(const uint32_t*)&AsH[rA * A_PITCH + cA];
                aH[mt][1] = *(const uint32_t*)&AsH[(rA + 8) * A_PITCH + cA];
                aH[mt][2] = *(const uint32_t*)&AsH[rA * A_PITCH + cA + 8];
                aH[mt][3] = *(const uint32_t*)&AsH[(rA + 8) * A_PITCH + cA + 8];
            }
#pragma unroll
            for (int nt = 0; nt < 8; nt++) {
                int col = wn * 64 + nt * 8 + g;
                int rb  = (ks + tig * 2) * B_PITCH + col;
                uint32_t bH0 = pack2h(BsH[rb], BsH[rb + B_PITCH]);
                int rb8 = rb + 8 * B_PITCH;
                uint32_t bH1 = pack2h(BsH[rb8], BsH[rb8 + B_PITCH]);
#pragma unroll
                for (int mt = 0; mt < 2; mt++)
                    mma16816h(acc[mt][nt], aH[mt], bH0, bH1);
            }
        }
        __syncthreads();
    }

#pragma unroll
    for (int mt = 0; mt < 2; mt++) {
        int r = r0 + wm * 32 + mt * 16 + g;
#pragma unroll
        for (int nt = 0; nt < 8; nt++) {
            int col = c0 + wn * 64 + nt * 8 + tig * 2;
            *(float2*)(C + (size_t)r * ldc + col) =
                make_float2(acc[mt][nt][0], acc[mt][nt][1]);
            *(float2*)(C + (size_t)(r + 8) * ldc + col) =
                make_float2(acc[mt][nt][2], acc[mt][nt][3]);
        }
    }
}

// ---------------------------------------------------------------------------
// Tensor-core flash attention. Block = (b,h): 64 queries, 256 thr = 8 warps.
// 2 CTAs/SM: all 256 blocks resident in one wave.
// ---------------------------------------------------------------------------
#define QKP 72
#define SSP 36
#define PSP 40

__global__ __launch_bounds__(256, 2) void attn_mma_kernel(
    const __half* __restrict__ Qh,
    const __half* __restrict__ KVh,
    float* __restrict__ Aout)
{
    __shared__ __half Qs[64][QKP];
    __shared__ __half Ks[2][32][QKP];
    __shared__ __half Vs[2][32][QKP];
    __shared__ float  Ss[64][SSP];
    __shared__ __half Ps[64][PSP];
    __shared__ float  m_s[64], l_s[64], f_s[64];

    const int bh = blockIdx.x;
    const int b = bh >> 4, h = bh & 15;
    const __half* Qb = Qh  + (size_t)(b * 64) * 1024 + h * 64;
    const __half* Kb = KVh + (size_t)b * 2048 * 2048 + h * 64;
    const __half* Vb = Kb + 1024;

    const int tid  = threadIdx.x;
    const int lane = tid & 31;
    const int w    = tid >> 5;
    const int g    = lane >> 2;
    const int tig  = lane & 3;
    const int mt   = w & 3;
    const int nt   = w >> 2;

    for (int i = tid; i < 1024; i += 256) {
        int t = i >> 4, h8 = (i & 15) * 4;
        *(uint2*)&Qs[t][h8] = *(const uint2*)(Qb + (size_t)t * 1024 + h8);
    }
    if (tid < 64) { m_s[tid] = -1e30f; l_s[tid] = 0.f; f_s[tid] = 1.f; }

    float o[4][4];
#pragma unroll
    for (int i = 0; i < 4; i++)
#pragma unroll
        for (int j = 0; j < 4; j++) o[i][j] = 0.f;

    auto load_kv = [&](int st, int s0) {
#pragma unroll
        for (int j = 0; j < 2; j++) {
            int c   = tid + 256 * j;
            int isV = c >> 8;
            int cc  = c & 255;
            int row = cc >> 3;
            int h8  = (cc & 7) * 8;
            const __half* gsrc = (isV ? Vb : Kb) + (size_t)(s0 + row) * 2048 + h8;
            __half* sdst = isV ? &Vs[st][row][h8] : &Ks[st][row][h8];
            cp16(sdst, gsrc);
        }
    };

    load_kv(0, 0);
    asm volatile("cp.async.commit_group;" ::: "memory");

    int buf = 0;
    for (int it = 0; it < 64; it++) {
        if (it < 63) {
            load_kv(buf ^ 1, (it + 1) * 32);
            asm volatile("cp.async.commit_group;" ::: "memory");
            asm volatile("cp.async.wait_group 1;" ::: "memory");
        } else {
            asm volatile("cp.async.wait_group 0;" ::: "memory");
        }
        __syncthreads();

        // ---- QK^T ----
        float sc[2][4];
#pragma unroll
        for (int j = 0; j < 2; j++)
#pragma unroll
            for (int q = 0; q < 4; q++) sc[j][q] = 0.f;
#pragma unroll
        for (int ks = 0; ks < 4; ks++) {
            uint32_t a[4];
            int cA = 16 * ks + 2 * tig;
            a[0] = *(const uint32_t*)&Qs[16 * mt + g][cA];
            a[1] = *(const uint32_t*)&Qs[16 * mt + g + 8][cA];
            a[2] = *(const uint32_t*)&Qs[16 * mt + g][cA + 8];
            a[3] = *(const uint32_t*)&Qs[16 * mt + g + 8][cA + 8];
#pragma unroll
            for (int j = 0; j < 2; j++) {
                int krow = 16 * nt + 8 * j + g;
                uint32_t b0 = *(const uint32_t*)&Ks[buf][krow][cA];
                uint32_t b1 = *(const uint32_t*)&Ks[buf][krow][cA + 8];
                mma16816h(sc[j], a, b0, b1);
            }
        }
#pragma unroll
        for (int j = 0; j < 2; j++) {
            *(float2*)&Ss[16 * mt + g][16 * nt + 8 * j + 2 * tig]     = make_float2(sc[j][0], sc[j][1]);
            *(float2*)&Ss[16 * mt + g + 8][16 * nt + 8 * j + 2 * tig] = make_float2(sc[j][2], sc[j][3]);
        }
        __syncthreads();

        // ---- online softmax: 4 threads/row, 8 cols each ----
        {
            int row = tid >> 2;
            int c0  = (tid & 3) * 8;
            float4 sa = *(const float4*)&Ss[row][c0];
            float4 sb = *(const float4*)&Ss[row][c0 + 4];
            float cmax = fmaxf(fmaxf(fmaxf(sa.x, sa.y), fmaxf(sa.z, sa.w)),
                               fmaxf(fmaxf(sb.x, sb.y), fmaxf(sb.z, sb.w)));
#pragma unroll
            for (int off = 2; off > 0; off >>= 1)
                cmax = fmaxf(cmax, __shfl_xor_sync(0xffffffffu, cmax, off, 4));
            float mo = m_s[row];
            float mn = fmaxf(mo, cmax);
            float f  = __expf(mo - mn);
            float p0 = __expf(sa.x - mn), p1 = __expf(sa.y - mn);
            float p2 = __expf(sa.z - mn), p3 = __expf(sa.w - mn);
            float p4 = __expf(sb.x - mn), p5 = __expf(sb.y - mn);
            float p6 = __expf(sb.z - mn), p7 = __expf(sb.w - mn);
            float cs = (p0 + p1 + p2 + p3) + (p4 + p5 + p6 + p7);
#pragma unroll
            for (int off = 2; off > 0; off >>= 1)
                cs += __shfl_xor_sync(0xffffffffu, cs, off, 4);
            if ((tid & 3) == 0) {
                m_s[row] = mn;
                l_s[row] = l_s[row] * f + cs;
                f_s[row] = f;
            }
            *(__half2*)&Ps[row][c0]     = __floats2half2_rn(p0, p1);
            *(__half2*)&Ps[row][c0 + 2] = __floats2half2_rn(p2, p3);
            *(__half2*)&Ps[row][c0 + 4] = __floats2half2_rn(p4, p5);
            *(__half2*)&Ps[row][c0 + 6] = __floats2half2_rn(p6, p7);
        }
        __syncthreads();

        // ---- P @ V ----
        {
            float f0 = f_s[16 * mt + g];
            float f1 = f_s[16 * mt + g + 8];
#pragma unroll
            for (int j = 0; j < 4; j++) {
                o[j][0] *= f0; o[j][1] *= f0;
                o[j][2] *= f1; o[j][3] *= f1;
            }
#pragma unroll
            for (int ks = 0; ks < 2; ks++) {
                uint32_t a[4];
                int cA = 16 * ks + 2 * tig;
                a[0] = *(const uint32_t*)&Ps[16 * mt + g][cA];
                a[1] = *(const uint32_t*)&Ps[16 * mt + g + 8][cA];
                a[2] = *(const uint32_t*)&Ps[16 * mt + g][cA + 8];
                a[3] = *(const uint32_t*)&Ps[16 * mt + g + 8][cA + 8];
#pragma unroll
                for (int j = 0; j < 4; j++) {
                    int n  = 32 * nt + 8 * j + g;
                    int k0 = 16 * ks + 2 * tig;
                    uint32_t b0 = pack2h(__half_as_ushort(Vs[buf][k0][n]),
                                         __half_as_ushort(Vs[buf][k0 + 1][n]));
                    uint32_t b1 = pack2h(__half_as_ushort(Vs[buf][k0 + 8][n]),
                                         __half_as_ushort(Vs[buf][k0 + 9][n]));
                    mma16816h(o[j], a, b0, b1);
                }
            }
        }
        __syncthreads();
        buf ^= 1;
    }

    // ---- write O ----
    {
        int r0g = 16 * mt + g;
        float inv0 = 1.f / l_s[r0g];
        float inv1 = 1.f / l_s[r0g + 8];
        float* Ap = Aout + (size_t)(b * 64) * 1024 + h * 64;
#pragma unroll
        for (int j = 0; j < 4; j++) {
            int col = 32 * nt + 8 * j + 2 * tig;
            *(float2*)(Ap + (size_t)r0g * 1024 + col) =
                make_float2(o[j][0] * inv0, o[j][1] * inv0);
            *(float2*)(Ap + (size_t)(r0g + 8) * 1024 + col) =
                make_float2(o[j][2] * inv1, o[j][3] * inv1);
        }
    }
}

// ---------------------------------------------------------------------------
// out[row] = LayerNorm(sum_z part[z][row] + bias + res[row]) * g + b
// (row length 256; 4 split-K partials)
// ---------------------------------------------------------------------------
__global__ __launch_bounds__(256) void add_ln4_kernel(
    const float* __restrict__ part, size_t splitStride,
    const float* __restrict__ bias,
    const float* __restrict__ res,
    const float* __restrict__ g,
    const float* __restrict__ bta,
    float* __restrict__ out)
{
    const int row = blockIdx.x;
    const int t = threadIdx.x;
    const size_t idx = (size_t)row * 256 + t;

    float v = bias[t] + res[idx]
            + part[idx] + part[idx + splitStride]
            + part[idx + 2 * splitStride] + part[idx + 3 * splitStride];
    float s = v, s2 = v * v;
#pragma unroll
    for (int off = 16; off > 0; off >>= 1) {
        s  += __shfl_xor_sync(0xffffffffu, s,  off);
        s2 += __shfl_xor_sync(0xffffffffu, s2, off);
    }
    __shared__ float rs[8], rs2[8];
    const int w = t >> 5, lane = t & 31;
    if (lane == 0) { rs[w] = s; rs2[w] = s2; }
    __syncthreads();
    if (t < 32) {
        s  = (t < 8) ? rs[t]  : 0.f;
        s2 = (t < 8) ? rs2[t] : 0.f;
#pragma unroll
        for (int off = 4; off > 0; off >>= 1) {
            s  += __shfl_xor_sync(0xffffffffu, s,  off);
            s2 += __shfl_xor_sync(0xffffffffu, s2, off);
        }
        if (t == 0) { rs[0] = s; rs2[0] = s2; }
    }
    __syncthreads();
    float mean = rs[0] * (1.f / 256.f);
    float var  = rs2[0] * (1.f / 256.f) - mean * mean;
    out[idx] = (v - mean) * rsqrtf(var + 1e-5f) * g[t] + bta[t];
}

// ---------------------------------------------------------------------------
extern "C" void kernel_launch(void* const* d_in, const int* in_sizes, int n_in,
                              void* d_out, int out_size)
{
    const float* src  = (const float*)d_in[0];
    const float* tgt  = (const float*)d_in[1];
    const float* Wq   = (const float*)d_in[2];
    const float* bq   = (const float*)d_in[3];
    const float* Wk   = (const float*)d_in[4];
    const float* bk   = (const float*)d_in[5];
    const float* Wv   = (const float*)d_in[6];
    const float* bv   = (const float*)d_in[7];
    const float* Wo   = (const float*)d_in[8];
    const float* bo   = (const float*)d_in[9];
    const float* ln1g = (const float*)d_in[10];
    const float* ln1b = (const float*)d_in[11];
    const float* W1   = (const float*)d_in[12];
    const float* bf1  = (const float*)d_in[13];
    const float* W2   = (const float*)d_in[14];
    const float* bf2  = (const float*)d_in[15];
    const float* ln3g = (const float*)d_in[16];
    const float* ln3b = (const float*)d_in[17];
    float* out = (float*)d_out;

    float *Ap, *F1, *X1;
    __half *KVh, *Qh;
    ushort_t *srcH, *wkvH;
    cudaGetSymbolAddress((void**)&KVh, g_KVh);
    cudaGetSymbolAddress((void**)&Qh, g_Qh);
    cudaGetSymbolAddress((void**)&Ap, g_A);
    cudaGetSymbolAddress((void**)&F1, g_F1);
    cudaGetSymbolAddress((void**)&X1, g_X1);
    cudaGetSymbolAddress((void**)&srcH, g_srcH);
    cudaGetSymbolAddress((void**)&wkvH, g_wkvH);

    static bool attr_set = false;
    if (!attr_set) {
        cudaFuncSetAttribute(gemm_kv_f16,
                             cudaFuncAttributeMaxDynamicSharedMemorySize, KV_SMEM_BYTES);
        attr_set = true;
    }

    const dim3 blk(256);
    const size_t PSTRIDE = (size_t)1024 * 256;   // split-K partial stride

    // 1-2: pre-pass conversions
    convert_src_kernel<<<(32768 * 1024 / 4 + 255) / 256, blk>>>(src, srcH, 32768 * 1024 / 4);
    conv_wkv_kernel<<<dim3(64, 32), dim3(32, 8)>>>(Wk, Wv, wkvH);

    // 3: Q projection -> fp16 with 1/8 scale folded
    gemm_tc<false, true><<<dim3(8, 8), blk>>>(tgt, 256, Wq, 1024, bq, Qh, 1024, 256, 0.125f);

    // 4: fused K|V projection (profiled slot; at issue floor)
    gemm_kv_f16<<<dim3(16, 256), blk, KV_SMEM_BYTES>>>(srcH, wkvH, bk, bv, KVh);

    // 5: tensor-core attention (2 CTAs/SM, single wave)
    attn_mma_kernel<<<256, blk>>>(Qh, KVh, Ap);

    // 6-7: output projection (split-K x4 -> F1 partials) + residual + LN1
    gemm_splitk4<<<dim3(2, 8, 4), blk>>>(Ap, 1024, Wo, 256, F1, 256, 1024, PSTRIDE);
    add_ln4_kernel<<<1024, 256>>>(F1, PSTRIDE, bo, tgt, ln1g, ln1b, X1);

    // 8: FFN up (relu) -> F1 (overwrites partials, already consumed)
    gemm_tc<true, false><<<dim3(8, 8), blk>>>(X1, 256, W1, 1024, bf1, F1, 1024, 256, 1.f);

    // 9-10: FFN down (split-K x4 -> Ap partials) + residual + LN3 -> out
    gemm_splitk4<<<dim3(2, 8, 4), blk>>>(F1, 1024, W2, 256, Ap, 256, 1024, PSTRIDE);
    add_ln4_kernel<<<1024, 256>>>(Ap, PSTRIDE, bf2, X1, ln3g, ln3b, out);
}